// round 9
// baseline (speedup 1.0000x reference)
#include <cuda_runtime.h>
#include <cuda_bf16.h>
#include <math.h>

// ---------------- problem constants ----------------
#define BB   16
#define SS   32
#define NTT  2029
#define NN   256
#define PIX  (NN*NN)            // 65536
#define IMG  (BB*PIX)           // 1048576

// ---------------- scratch (device globals; referenced ONLY from device code) --
__device__ float g_rec [BB*PIX];                 // 4 MB
__device__ float g_h0  [BB*64 *128*128];         // 64 MB
__device__ float g_h1  [BB*128*64 *64 ];         // 32 MB
__device__ float g_h2  [BB*256*32 *32 ];         // 16 MB
__device__ float g_h3  [BB*512*16 *16 ];         // 8 MB
__device__ float g_h4  [BB*512*8  *8  ];         // 2 MB
__device__ float g_u4  [BB*512*16 *16 ];         // 8 MB
__device__ float g_u3  [BB*256*32 *32 ];         // 16 MB
__device__ float g_u2  [BB*128*64 *64 ];         // 32 MB
__device__ float g_u1  [BB*64 *128*128];         // 64 MB
__device__ float g_wpack[4*512*512*4];           // 16 MB (per-parity repacked deconv weights)
__device__ float g_mm[2];
__device__ float g_scale[512];
__device__ float g_shift[512];

// ---------------- tf32 helpers ----------------
__device__ __forceinline__ float tf32f(float x)
{
    unsigned r;
    asm("cvt.rna.tf32.f32 %0, %1;" : "=r"(r) : "f"(x));
    return __uint_as_float(r);
}

__device__ __forceinline__ void mma_tf32(float c[4],
                                         const unsigned a[4],
                                         unsigned b0, unsigned b1)
{
    asm("mma.sync.aligned.m16n8k8.row.col.f32.tf32.tf32.f32 "
        "{%0,%1,%2,%3}, {%4,%5,%6,%7}, {%8,%9}, {%0,%1,%2,%3};"
        : "+f"(c[0]), "+f"(c[1]), "+f"(c[2]), "+f"(c[3])
        : "r"(a[0]), "r"(a[1]), "r"(a[2]), "r"(a[3]), "r"(b0), "r"(b1));
}

// ---------------- backprojection (bit-exact R4/R6 form — DO NOT TOUCH) -------
__global__ void k_backproject(const float* __restrict__ sig,
                              const float* __restrict__ trans)
{
    int idx = blockIdx.x * blockDim.x + threadIdx.x;
    if (idx >= PIX) return;
    int j = idx & 255;
    int i = idx >> 8;

    const float startf = -0.0125f;
    const float stopf  =  0.0125f;
    float stepj = __fdiv_rn((float)j, 255.0f);
    float stepi = __fdiv_rn((float)i, 255.0f);
    float cj = __fadd_rn(__fmul_rn(startf, __fsub_rn(1.0f, stepj)),
                         __fmul_rn(stopf,  stepj));
    float ci = __fadd_rn(__fmul_rn(startf, __fsub_rn(1.0f, stepi)),
                         __fmul_rn(stopf,  stepi));

    float acc[BB];
#pragma unroll
    for (int b = 0; b < BB; b++) acc[b] = 0.f;

    for (int s = 0; s < SS; s++) {
        float dx = __fsub_rn(cj, __ldg(&trans[2*s+0]));
        float dy = __fsub_rn(ci, __ldg(&trans[2*s+1]));
        float dd = __fadd_rn(__fmul_rn(dx, dx), __fmul_rn(dy, dy));
        float d  = __fsqrt_rn(dd);
        float v  = __fadd_rn(__fsub_rn(__fdiv_rn(__fmul_rn(d, 40000000.0f),
                                                 1572.0f),
                                       113.0f),
                             1.0f);
        int t = (int)rintf(v);
        t = max(0, min(t, NTT-1));
        const float* sp = sig + (size_t)t * SS + s;
#pragma unroll
        for (int b = 0; b < BB; b++)
            acc[b] += __ldg(sp + (size_t)b * NTT * SS);
    }
#pragma unroll
    for (int b = 0; b < BB; b++)
        g_rec[(size_t)b * PIX + idx] = acc[b] * (1.0f / 32.0f);
}

// ---------------- global min/max ----------------
__device__ void atomicMinF(float* a, float v) {
    int old = __float_as_int(*a);
    while (v < __int_as_float(old)) {
        int prev = atomicCAS((int*)a, old, __float_as_int(v));
        if (prev == old) break;
        old = prev;
    }
}
__device__ void atomicMaxF(float* a, float v) {
    int old = __float_as_int(*a);
    while (v > __int_as_float(old)) {
        int prev = atomicCAS((int*)a, old, __float_as_int(v));
        if (prev == old) break;
        old = prev;
    }
}
__global__ void k_minmax_init() { g_mm[0] = INFINITY; g_mm[1] = -INFINITY; }

__global__ void k_minmax_reduce()
{
    float mn = INFINITY, mx = -INFINITY;
    for (int i = blockIdx.x * blockDim.x + threadIdx.x; i < IMG; i += gridDim.x * blockDim.x) {
        float v = g_rec[i];
        mn = fminf(mn, v);
        mx = fmaxf(mx, v);
    }
    __shared__ float smn[256], smx[256];
    int t = threadIdx.x;
    smn[t] = mn; smx[t] = mx;
    __syncthreads();
    for (int o = 128; o > 0; o >>= 1) {
        if (t < o) { smn[t] = fminf(smn[t], smn[t+o]); smx[t] = fmaxf(smx[t], smx[t+o]); }
        __syncthreads();
    }
    if (t == 0) { atomicMinF(&g_mm[0], smn[0]); atomicMaxF(&g_mm[1], smx[0]); }
}

__global__ void k_normalize(float* __restrict__ out_rec, int copy_out)
{
    int i = blockIdx.x * blockDim.x + threadIdx.x;
    if (i >= IMG) return;
    float mn = g_mm[0], mx = g_mm[1];
    float v = __fdiv_rn(__fsub_rn(g_rec[i], mn), __fsub_rn(mx, mn));
    g_rec[i] = v;
    if (copy_out) out_rec[i] = v;
}

// =====================================================================
// conv stride-2 k4 p1 — implicit GEMM v3 (3xTF32 tensor cores)
// 64x64 tile, 256 threads (8 warps, 4x2 warp grid of 16x32 sub-tiles),
// staging identical to v1.5; operands Dekker-split into tf32 hi/lo
// planes; inner loop = mma.m16n8k8 with hi*lo + lo*hi + hi*hi.
// =====================================================================
template<int Cin, int Hi, int Wi, int Cout, int ACT>
__device__ __forceinline__ void conv_v3(const float* __restrict__ in,
                                        const float* __restrict__ w,
                                        float* __restrict__ out)
{
    constexpr int Ho = Hi >> 1, Wo = Wi >> 1;
    constexpr int HoWo = Ho * Wo;
    constexpr int HiWi = Hi * Wi;
    const int m0 = blockIdx.y * 64;
    const int p0 = blockIdx.x * 64;

    __shared__ __align__(16) float AsH[2][16][72], AsL[2][16][72];
    __shared__ __align__(16) float BsH[2][16][72], BsL[2][16][72];

    const int tid  = threadIdx.x;
    const int kk   = tid & 15;      // staging tap index
    const int rowq = tid >> 4;      // staging row group
    const int ky = kk >> 2, kx = kk & 3;

    const int wid  = tid >> 5;      // 0..7
    const int lane = tid & 31;
    const int wm   = wid & 3;       // m sub-tile: 16*wm
    const int wn   = wid >> 2;      // n sub-tile: 32*wn
    const int grp  = lane >> 2;     // 0..7
    const int qd   = lane & 3;      // 0..3

    int woff[4], bofs[4];
#pragma unroll
    for (int q = 0; q < 4; q++) {
        int n = rowq + 16 * q;
        woff[q] = (m0 + n) * Cin * 16 + kk;
        int p = p0 + n;
        int b = p / HoWo; int r = p - b * HoWo;
        int y = r / Wo;   int x = r - y * Wo;
        int iy = 2*y - 1 + ky, ix = 2*x - 1 + kx;
        bool v = iy >= 0 && iy < Hi && ix >= 0 && ix < Wi;
        bofs[q] = v ? (b * Cin * HiWi + iy * Wi + ix) : -1;
    }

    float aR[4], bR[4];
    // prologue: stage chunk 0
#pragma unroll
    for (int q = 0; q < 4; q++) {
        aR[q] = __ldg(w + woff[q]);
        float v = 0.f;
        if (bofs[q] >= 0) {
            v = __ldg(in + bofs[q]);
            if (ACT) v = (v >= 0.f) ? v : 0.2f * v;
        }
        bR[q] = v;
    }
#pragma unroll
    for (int q = 0; q < 4; q++) {
        int col = rowq + 16 * q;
        float ah = tf32f(aR[q]);
        AsH[0][kk][col] = ah;
        AsL[0][kk][col] = tf32f(aR[q] - ah);
        float bh = tf32f(bR[q]);
        BsH[0][kk][col] = bh;
        BsL[0][kk][col] = tf32f(bR[q] - bh);
    }
    __syncthreads();

    float acc[4][4];
#pragma unroll
    for (int t = 0; t < 4; t++)
#pragma unroll
        for (int j = 0; j < 4; j++) acc[t][j] = 0.f;

    int buf = 0;
    for (int cci = 0; cci < Cin; cci++) {
        const bool more = (cci + 1 < Cin);
        if (more) {
            const float* wp = w + (size_t)(cci + 1) * 16;
            const float* ip = in + (size_t)(cci + 1) * HiWi;
#pragma unroll
            for (int q = 0; q < 4; q++) {
                aR[q] = __ldg(wp + woff[q]);
                float v = 0.f;
                if (bofs[q] >= 0) {
                    v = __ldg(ip + bofs[q]);
                    if (ACT) v = (v >= 0.f) ? v : 0.2f * v;
                }
                bR[q] = v;
            }
        }
        // compute: 2 k-steps of 8
#pragma unroll
        for (int ks = 0; ks < 2; ks++) {
            int k0 = 8 * ks;
            int mrow = 16 * wm + grp;
            unsigned aH[4], aL[4];
            aH[0] = __float_as_uint(AsH[buf][k0 + qd    ][mrow    ]);
            aH[1] = __float_as_uint(AsH[buf][k0 + qd    ][mrow + 8]);
            aH[2] = __float_as_uint(AsH[buf][k0 + qd + 4][mrow    ]);
            aH[3] = __float_as_uint(AsH[buf][k0 + qd + 4][mrow + 8]);
            aL[0] = __float_as_uint(AsL[buf][k0 + qd    ][mrow    ]);
            aL[1] = __float_as_uint(AsL[buf][k0 + qd    ][mrow + 8]);
            aL[2] = __float_as_uint(AsL[buf][k0 + qd + 4][mrow    ]);
            aL[3] = __float_as_uint(AsL[buf][k0 + qd + 4][mrow + 8]);
#pragma unroll
            for (int t = 0; t < 4; t++) {
                int nc = 32 * wn + 8 * t + grp;
                unsigned bH0 = __float_as_uint(BsH[buf][k0 + qd    ][nc]);
                unsigned bH1 = __float_as_uint(BsH[buf][k0 + qd + 4][nc]);
                unsigned bL0 = __float_as_uint(BsL[buf][k0 + qd    ][nc]);
                unsigned bL1 = __float_as_uint(BsL[buf][k0 + qd + 4][nc]);
                mma_tf32(acc[t], aH, bL0, bL1);
                mma_tf32(acc[t], aL, bH0, bH1);
                mma_tf32(acc[t], aH, bH0, bH1);
            }
        }
        if (more) {
            int nb = buf ^ 1;
#pragma unroll
            for (int q = 0; q < 4; q++) {
                int col = rowq + 16 * q;
                float ah = tf32f(aR[q]);
                AsH[nb][kk][col] = ah;
                AsL[nb][kk][col] = tf32f(aR[q] - ah);
                float bh = tf32f(bR[q]);
                BsH[nb][kk][col] = bh;
                BsL[nb][kk][col] = tf32f(bR[q] - bh);
            }
            __syncthreads();
            buf = nb;
        }
    }

    // epilogue: c0/c1 are n-contiguous pairs -> float2 stores
#pragma unroll
    for (int t = 0; t < 4; t++) {
        int p = p0 + 32 * wn + 8 * t + 2 * qd;
        int b = p / HoWo; int r = p - b * HoWo;
        int m1 = m0 + 16 * wm + grp;
        float2 v0 = make_float2(acc[t][0], acc[t][1]);
        float2 v1 = make_float2(acc[t][2], acc[t][3]);
        *(float2*)(&out[(size_t)(b * Cout + m1    ) * HoWo + r]) = v0;
        *(float2*)(&out[(size_t)(b * Cout + m1 + 8) * HoWo + r]) = v1;
    }
}

__global__ void __launch_bounds__(256,2) k_conv_d0(const float* __restrict__ w)
{ conv_v3<1,256,256,64,0>(g_rec, w, g_h0); }
__global__ void __launch_bounds__(256,2) k_conv_d1(const float* __restrict__ w)
{ conv_v3<64,128,128,128,1>(g_h0, w, g_h1); }
__global__ void __launch_bounds__(256,2) k_conv_d2(const float* __restrict__ w)
{ conv_v3<128,64,64,256,1>(g_h1, w, g_h2); }
__global__ void __launch_bounds__(256,2) k_conv_d3(const float* __restrict__ w)
{ conv_v3<256,32,32,512,1>(g_h2, w, g_h3); }
__global__ void __launch_bounds__(256,2) k_conv_d4(const float* __restrict__ w)
{ conv_v3<512,16,16,512,1>(g_h3, w, g_h4); }

// ---------------- deconv weight repack (per-parity) ----------------
__global__ void k_repack(const float* __restrict__ w, int Cin, int Cout)
{
    int idx = blockIdx.x * blockDim.x + threadIdx.x;
    int total = 4 * Cout * Cin * 4;
    if (idx >= total) return;
    int t  = idx & 3;
    int tmp = idx >> 2;
    int ci = tmp % Cin; tmp /= Cin;
    int m  = tmp % Cout;
    int pz = tmp / Cout;
    int py = pz >> 1, px = pz & 1;
    int di = t >> 1,  dj = t & 1;
    int ky = py ? (1 + 2*di) : (2*di);
    int kx = px ? (1 + 2*dj) : (2*dj);
    g_wpack[idx] = w[(((size_t)ci * Cout + m) * 4 + (3 - ky)) * 4 + (3 - kx)];
}

// =====================================================================
// transposed conv stride-2 k4 p2 — parity implicit GEMM v3 (3xTF32)
// =====================================================================
template<int Cin, int C1, int Hi, int Wi, int Cout>
__device__ __forceinline__ void deconv_v3(const float* __restrict__ in1,
                                          const float* __restrict__ in2,
                                          float* __restrict__ out)
{
    constexpr int HiWi = Hi * Wi;
    constexpr int Wo = 2 * Wi;
    constexpr int HoWo = 4 * HiWi;
    constexpr int C2 = Cin - C1;
    constexpr int NCH = Cin / 4;
    const int pz = blockIdx.z;
    const int py = pz >> 1, px = pz & 1;
    const int m0 = blockIdx.y * 64;
    const int n0 = blockIdx.x * 64;

    __shared__ __align__(16) float AsH[2][16][72], AsL[2][16][72];
    __shared__ __align__(16) float BsH[2][16][72], BsL[2][16][72];

    const int tid  = threadIdx.x;
    const int kk   = tid & 15;      // cil*4 + t
    const int rowq = tid >> 4;
    const int cil = kk >> 2, tt = kk & 3;
    const int di = tt >> 1, dj = tt & 1;

    const int wid  = tid >> 5;
    const int lane = tid & 31;
    const int wm   = wid & 3;
    const int wn   = wid >> 2;
    const int grp  = lane >> 2;
    const int qd   = lane & 3;

    int woff[4], pixq[4], bq[4];
#pragma unroll
    for (int q = 0; q < 4; q++) {
        int n = n0 + rowq + 16 * q;
        int b = n / HiWi; int r = n - b * HiWi;
        int yy = r / Wi;  int xx = r - yy * Wi;
        int i = py ? (yy + di) : (yy - 1 + di);
        int j = px ? (xx + dj) : (xx - 1 + dj);
        bool v = i >= 0 && i < Hi && j >= 0 && j < Wi;
        pixq[q] = v ? (i * Wi + j) : -1;
        bq[q] = b;
        int m = m0 + rowq + 16 * q;
        woff[q] = ((pz * Cout + m) * Cin + cil) * 4 + tt;
    }

    float aR[4], bR[4];
    // prologue: chunk 0 (ci = cil)
#pragma unroll
    for (int q = 0; q < 4; q++) {
        aR[q] = g_wpack[woff[q]];
        float v = 0.f;
        if (pixq[q] >= 0) {
            const float* src = (cil < C1)
                ? in1 + (size_t)(bq[q] * C1 + cil) * HiWi
                : in2 + (size_t)(bq[q] * C2 + (cil - C1)) * HiWi;
            v = fmaxf(__ldg(src + pixq[q]), 0.f);
        }
        bR[q] = v;
    }
#pragma unroll
    for (int q = 0; q < 4; q++) {
        int col = rowq + 16 * q;
        float ah = tf32f(aR[q]);
        AsH[0][kk][col] = ah;
        AsL[0][kk][col] = tf32f(aR[q] - ah);
        float bh = tf32f(bR[q]);
        BsH[0][kk][col] = bh;
        BsL[0][kk][col] = tf32f(bR[q] - bh);
    }
    __syncthreads();

    float acc[4][4];
#pragma unroll
    for (int t = 0; t < 4; t++)
#pragma unroll
        for (int j = 0; j < 4; j++) acc[t][j] = 0.f;

    int buf = 0;
    for (int s = 0; s < NCH; s++) {
        const bool more = (s + 1 < NCH);
        if (more) {
            int ci = 4 * (s + 1) + cil;
#pragma unroll
            for (int q = 0; q < 4; q++) {
                aR[q] = g_wpack[woff[q] + (s + 1) * 16];
                float v = 0.f;
                if (pixq[q] >= 0) {
                    const float* src = (ci < C1)
                        ? in1 + (size_t)(bq[q] * C1 + ci) * HiWi
                        : in2 + (size_t)(bq[q] * C2 + (ci - C1)) * HiWi;
                    v = fmaxf(__ldg(src + pixq[q]), 0.f);
                }
                bR[q] = v;
            }
        }
#pragma unroll
        for (int ks = 0; ks < 2; ks++) {
            int k0 = 8 * ks;
            int mrow = 16 * wm + grp;
            unsigned aH[4], aL[4];
            aH[0] = __float_as_uint(AsH[buf][k0 + qd    ][mrow    ]);
            aH[1] = __float_as_uint(AsH[buf][k0 + qd    ][mrow + 8]);
            aH[2] = __float_as_uint(AsH[buf][k0 + qd + 4][mrow    ]);
            aH[3] = __float_as_uint(AsH[buf][k0 + qd + 4][mrow + 8]);
            aL[0] = __float_as_uint(AsL[buf][k0 + qd    ][mrow    ]);
            aL[1] = __float_as_uint(AsL[buf][k0 + qd    ][mrow + 8]);
            aL[2] = __float_as_uint(AsL[buf][k0 + qd + 4][mrow    ]);
            aL[3] = __float_as_uint(AsL[buf][k0 + qd + 4][mrow + 8]);
#pragma unroll
            for (int t = 0; t < 4; t++) {
                int nc = 32 * wn + 8 * t + grp;
                unsigned bH0 = __float_as_uint(BsH[buf][k0 + qd    ][nc]);
                unsigned bH1 = __float_as_uint(BsH[buf][k0 + qd + 4][nc]);
                unsigned bL0 = __float_as_uint(BsL[buf][k0 + qd    ][nc]);
                unsigned bL1 = __float_as_uint(BsL[buf][k0 + qd + 4][nc]);
                mma_tf32(acc[t], aH, bL0, bL1);
                mma_tf32(acc[t], aL, bH0, bH1);
                mma_tf32(acc[t], aH, bH0, bH1);
            }
        }
        if (more) {
            int nb = buf ^ 1;
#pragma unroll
            for (int q = 0; q < 4; q++) {
                int col = rowq + 16 * q;
                float ah = tf32f(aR[q]);
                AsH[nb][kk][col] = ah;
                AsL[nb][kk][col] = tf32f(aR[q] - ah);
                float bh = tf32f(bR[q]);
                BsH[nb][kk][col] = bh;
                BsL[nb][kk][col] = tf32f(bR[q] - bh);
            }
            __syncthreads();
            buf = nb;
        }
    }

    // epilogue: scatter by parity (scalar stores)
#pragma unroll
    for (int t = 0; t < 4; t++) {
#pragma unroll
        for (int half = 0; half < 2; half++) {
            int n = n0 + 32 * wn + 8 * t + 2 * qd + half;
            int b = n / HiWi; int r = n - b * HiWi;
            int yy = r / Wi;  int xx = r - yy * Wi;
            int y = 2 * yy + py, x = 2 * xx + px;
            int m1 = m0 + 16 * wm + grp;
            out[(size_t)(b * Cout + m1    ) * HoWo + y * Wo + x] = acc[t][half];
            out[(size_t)(b * Cout + m1 + 8) * HoWo + y * Wo + x] = acc[t][2 + half];
        }
    }
}

__global__ void __launch_bounds__(256,2) k_deconv_u4()
{ deconv_v3<512,512,8,8,512>(g_h4, g_h4, g_u4); }
__global__ void __launch_bounds__(256,2) k_deconv_u3()
{ deconv_v3<1024,512,16,16,256>(g_h3, g_u4, g_u3); }
__global__ void __launch_bounds__(256,2) k_deconv_u2()
{ deconv_v3<512,256,32,32,128>(g_h2, g_u3, g_u2); }
__global__ void __launch_bounds__(256,2) k_deconv_u1()
{ deconv_v3<256,128,64,64,64>(g_h1, g_u2, g_u1); }

// ---------------- batchnorm ----------------
template<int C, int HW>
__device__ __forceinline__ void bn_stats_body(const float* __restrict__ x,
                                              const float* __restrict__ g,
                                              const float* __restrict__ bet)
{
    int c = blockIdx.x;
    constexpr int per = BB * HW;
    double s = 0.0, s2 = 0.0;
    for (int i = threadIdx.x; i < per; i += blockDim.x) {
        int bb = i / HW; int r = i - bb * HW;
        float v = x[(size_t)(bb * C + c) * HW + r];
        s  += v;
        s2 += (double)v * (double)v;
    }
    __shared__ double sh1[256], sh2[256];
    int tidl = threadIdx.x;
    sh1[tidl] = s; sh2[tidl] = s2;
    __syncthreads();
    for (int o = 128; o > 0; o >>= 1) {
        if (tidl < o) { sh1[tidl] += sh1[tidl+o]; sh2[tidl] += sh2[tidl+o]; }
        __syncthreads();
    }
    if (tidl == 0) {
        double m   = sh1[0] / per;
        double var = sh2[0] / per - m * m;
        float sc = g[c] * (float)(1.0 / sqrt(var + 1e-5));
        g_scale[c] = sc;
        g_shift[c] = bet[c] - (float)m * sc;
    }
}

template<int C, int HW>
__device__ __forceinline__ void bn_apply_body(float* __restrict__ x)
{
    constexpr int total = BB * C * HW;
    int i = blockIdx.x * blockDim.x + threadIdx.x;
    if (i >= total) return;
    int c = (i / HW) % C;
    x[i] = x[i] * g_scale[c] + g_shift[c];
}

__global__ void k_bns_h1(const float* g, const float* b){ bn_stats_body<128,4096>(g_h1,g,b); }
__global__ void k_bna_h1(){ bn_apply_body<128,4096>(g_h1); }
__global__ void k_bns_h2(const float* g, const float* b){ bn_stats_body<256,1024>(g_h2,g,b); }
__global__ void k_bna_h2(){ bn_apply_body<256,1024>(g_h2); }
__global__ void k_bns_h3(const float* g, const float* b){ bn_stats_body<512,256>(g_h3,g,b); }
__global__ void k_bna_h3(){ bn_apply_body<512,256>(g_h3); }
__global__ void k_bns_u4(const float* g, const float* b){ bn_stats_body<512,256>(g_u4,g,b); }
__global__ void k_bna_u4(){ bn_apply_body<512,256>(g_u4); }
__global__ void k_bns_u3(const float* g, const float* b){ bn_stats_body<256,1024>(g_u3,g,b); }
__global__ void k_bna_u3(){ bn_apply_body<256,1024>(g_u3); }
__global__ void k_bns_u2(const float* g, const float* b){ bn_stats_body<128,4096>(g_u2,g,b); }
__global__ void k_bna_u2(){ bn_apply_body<128,4096>(g_u2); }
__global__ void k_bns_u1(const float* g, const float* b){ bn_stats_body<64,16384>(g_u1,g,b); }
__global__ void k_bna_u1(){ bn_apply_body<64,16384>(g_u1); }

// ---------------- final deconv u0: 2x2 output quad per thread ----------------
__global__ void k_deconv_u0(const float* __restrict__ w,     // (128,1,4,4)
                            const float* __restrict__ b0,
                            float* __restrict__ out)         // (16,1,256,256)
{
    __shared__ float ws[2048];
    for (int i = threadIdx.x; i < 2048; i += blockDim.x) ws[i] = w[i];
    __syncthreads();

    int idx = blockIdx.x * blockDim.x + threadIdx.x;   // over BB*128*128
    if (idx >= BB * 128 * 128) return;
    int xx = idx & 127;
    int yy = (idx >> 7) & 127;
    int b  = idx >> 14;

    const float* h0p = g_h0 + (size_t)b * 64 * 16384;
    const float* u1p = g_u1 + (size_t)b * 64 * 16384;

    float a00 = 0.f, a01 = 0.f, a10 = 0.f, a11 = 0.f;

    for (int ci = 0; ci < 128; ci++) {
        const float* src = (ci < 64) ? (h0p + ci * 16384)
                                     : (u1p + (ci - 64) * 16384);
        float v[3][3];
#pragma unroll
        for (int dy = 0; dy < 3; dy++) {
            int i = yy - 1 + dy;
#pragma unroll
            for (int dxx = 0; dxx < 3; dxx++) {
                int jx = xx - 1 + dxx;
                v[dy][dxx] = (i >= 0 && i < 128 && jx >= 0 && jx < 128)
                             ? fmaxf(__ldg(src + i * 128 + jx), 0.f) : 0.f;
            }
        }
        const float* wsr = ws + ci * 16;
#pragma unroll
        for (int di = 0; di < 2; di++)
#pragma unroll
            for (int dj = 0; dj < 2; dj++)
                a00 += v[di][dj] * wsr[(3 - 2*di) * 4 + (3 - 2*dj)];
#pragma unroll
        for (int di = 0; di < 2; di++)
#pragma unroll
            for (int dj = 0; dj < 2; dj++)
                a01 += v[di][dj+1] * wsr[(3 - 2*di) * 4 + (2 - 2*dj)];
#pragma unroll
        for (int di = 0; di < 2; di++)
#pragma unroll
            for (int dj = 0; dj < 2; dj++)
                a10 += v[di+1][dj] * wsr[(2 - 2*di) * 4 + (3 - 2*dj)];
#pragma unroll
        for (int di = 0; di < 2; di++)
#pragma unroll
            for (int dj = 0; dj < 2; dj++)
                a11 += v[di+1][dj+1] * wsr[(2 - 2*di) * 4 + (2 - 2*dj)];
    }

    float bias = __ldg(&b0[0]);
    int base = b * PIX + (2 * yy) * 256 + 2 * xx;
    out[base]       = 1.0f / (1.0f + expf(-(a00 + bias)));
    out[base + 1]   = 1.0f / (1.0f + expf(-(a01 + bias)));
    out[base + 256] = 1.0f / (1.0f + expf(-(a10 + bias)));
    out[base + 257] = 1.0f / (1.0f + expf(-(a11 + bias)));
}

// ---------------- driver ----------------
extern "C" void kernel_launch(void* const* d_in, const int* in_sizes, int n_in,
                              void* d_out, int out_size)
{
    const float* sig   = (const float*)d_in[0];
    const float* trans = (const float*)d_in[1];
    const float* w_d0  = (const float*)d_in[2];
    const float* w_d1  = (const float*)d_in[3];
    const float* g_d1  = (const float*)d_in[4];
    const float* b_d1  = (const float*)d_in[5];
    const float* w_d2  = (const float*)d_in[6];
    const float* g_d2  = (const float*)d_in[7];
    const float* b_d2  = (const float*)d_in[8];
    const float* w_d3  = (const float*)d_in[9];
    const float* g_d3  = (const float*)d_in[10];
    const float* b_d3  = (const float*)d_in[11];
    const float* w_d4  = (const float*)d_in[12];
    const float* w_u4  = (const float*)d_in[13];
    const float* g_u4p = (const float*)d_in[14];
    const float* b_u4p = (const float*)d_in[15];
    const float* w_u3  = (const float*)d_in[16];
    const float* g_u3p = (const float*)d_in[17];
    const float* b_u3p = (const float*)d_in[18];
    const float* w_u2  = (const float*)d_in[19];
    const float* g_u2p = (const float*)d_in[20];
    const float* b_u2p = (const float*)d_in[21];
    const float* w_u1  = (const float*)d_in[22];
    const float* g_u1p = (const float*)d_in[23];
    const float* b_u1p = (const float*)d_in[24];
    const float* w_u0  = (const float*)d_in[25];
    const float* b_u0  = (const float*)d_in[26];

    float* outp = (float*)d_out;
    float* out_rec = outp + IMG;
    int copy_rec = (out_size >= 2 * IMG) ? 1 : 0;

    // 1. backprojection + normalization (rec)
    k_backproject<<<PIX / 256, 256>>>(sig, trans);
    k_minmax_init<<<1, 1>>>();
    k_minmax_reduce<<<256, 256>>>();
    k_normalize<<<(IMG + 255) / 256, 256>>>(out_rec, copy_rec);

    // 2. encoder (grid: x = Ptot/64, y = Cout/64; 256 threads)
    k_conv_d0<<<dim3(4096, 1), 256>>>(w_d0);
    k_conv_d1<<<dim3(1024, 2), 256>>>(w_d1);
    k_bns_h1<<<128, 256>>>(g_d1, b_d1);
    k_bna_h1<<<BB*128*4096/256, 256>>>();
    k_conv_d2<<<dim3(256,  4), 256>>>(w_d2);
    k_bns_h2<<<256, 256>>>(g_d2, b_d2);
    k_bna_h2<<<BB*256*1024/256, 256>>>();
    k_conv_d3<<<dim3(64,   8), 256>>>(w_d3);
    k_bns_h3<<<512, 256>>>(g_d3, b_d3);
    k_bna_h3<<<BB*512*256/256, 256>>>();
    k_conv_d4<<<dim3(16,   8), 256>>>(w_d4);

    // 3. decoder (grid: x = Ncls/64, y = Cout/64, z = parity; 256 threads)
    k_repack<<<(512*512*16 + 255)/256, 256>>>(w_u4, 512, 512);
    k_deconv_u4<<<dim3(16,  8, 4), 256>>>();
    k_bns_u4<<<512, 256>>>(g_u4p, b_u4p);
    k_bna_u4<<<BB*512*256/256, 256>>>();

    k_repack<<<(1024*256*16 + 255)/256, 256>>>(w_u3, 1024, 256);
    k_deconv_u3<<<dim3(64,  4, 4), 256>>>();
    k_bns_u3<<<256, 256>>>(g_u3p, b_u3p);
    k_bna_u3<<<BB*256*1024/256, 256>>>();

    k_repack<<<(512*128*16 + 255)/256, 256>>>(w_u2, 512, 128);
    k_deconv_u2<<<dim3(256, 2, 4), 256>>>();
    k_bns_u2<<<128, 256>>>(g_u2p, b_u2p);
    k_bna_u2<<<BB*128*4096/256, 256>>>();

    k_repack<<<(256*64*16 + 255)/256, 256>>>(w_u1, 256, 64);
    k_deconv_u1<<<dim3(1024, 1, 4), 256>>>();
    k_bns_u1<<<64, 256>>>(g_u1p, b_u1p);
    k_bna_u1<<<BB*64*16384/256, 256>>>();

    // 4. final layer: 2x2 quad per thread, fused bias + sigmoid
    k_deconv_u0<<<(BB*128*128 + 255) / 256, 256>>>(w_u0, b_u0, outp);
}

// round 10
// speedup vs baseline: 1.0049x; 1.0049x over previous
#include <cuda_runtime.h>
#include <cuda_bf16.h>
#include <math.h>

// ---------------- problem constants ----------------
#define BB   16
#define SS   32
#define NTT  2029
#define NN   256
#define PIX  (NN*NN)            // 65536
#define IMG  (BB*PIX)           // 1048576

// ---------------- scratch (device globals; referenced ONLY from device code) --
__device__ float g_rec [BB*PIX];                 // 4 MB
__device__ float g_h0  [BB*64 *128*128];         // 64 MB
__device__ float g_h1  [BB*128*64 *64 ];         // 32 MB
__device__ float g_h2  [BB*256*32 *32 ];         // 16 MB
__device__ float g_h3  [BB*512*16 *16 ];         // 8 MB
__device__ float g_h4  [BB*512*8  *8  ];         // 2 MB
__device__ float g_u4  [BB*512*16 *16 ];         // 8 MB
__device__ float g_u3  [BB*256*32 *32 ];         // 16 MB
__device__ float g_u2  [BB*128*64 *64 ];         // 32 MB
__device__ float g_u1  [BB*64 *128*128];         // 64 MB
__device__ float g_wpack[4*512*512*4];           // 16 MB (per-parity repacked deconv weights)
__device__ float g_mm[2];
__device__ float g_scale[512];
__device__ float g_shift[512];

// ---------------- tf32 helpers ----------------
__device__ __forceinline__ float tf32f(float x)
{
    unsigned r;
    asm("cvt.rna.tf32.f32 %0, %1;" : "=r"(r) : "f"(x));
    return __uint_as_float(r);
}

__device__ __forceinline__ void mma_tf32(float c[4],
                                         const unsigned a[4],
                                         unsigned b0, unsigned b1)
{
    asm("mma.sync.aligned.m16n8k8.row.col.f32.tf32.tf32.f32 "
        "{%0,%1,%2,%3}, {%4,%5,%6,%7}, {%8,%9}, {%0,%1,%2,%3};"
        : "+f"(c[0]), "+f"(c[1]), "+f"(c[2]), "+f"(c[3])
        : "r"(a[0]), "r"(a[1]), "r"(a[2]), "r"(a[3]), "r"(b0), "r"(b1));
}

// ---------------- backprojection (bit-exact R4/R6 form — DO NOT TOUCH) -------
__global__ void k_backproject(const float* __restrict__ sig,
                              const float* __restrict__ trans)
{
    int idx = blockIdx.x * blockDim.x + threadIdx.x;
    if (idx >= PIX) return;
    int j = idx & 255;
    int i = idx >> 8;

    const float startf = -0.0125f;
    const float stopf  =  0.0125f;
    float stepj = __fdiv_rn((float)j, 255.0f);
    float stepi = __fdiv_rn((float)i, 255.0f);
    float cj = __fadd_rn(__fmul_rn(startf, __fsub_rn(1.0f, stepj)),
                         __fmul_rn(stopf,  stepj));
    float ci = __fadd_rn(__fmul_rn(startf, __fsub_rn(1.0f, stepi)),
                         __fmul_rn(stopf,  stepi));

    float acc[BB];
#pragma unroll
    for (int b = 0; b < BB; b++) acc[b] = 0.f;

    for (int s = 0; s < SS; s++) {
        float dx = __fsub_rn(cj, __ldg(&trans[2*s+0]));
        float dy = __fsub_rn(ci, __ldg(&trans[2*s+1]));
        float dd = __fadd_rn(__fmul_rn(dx, dx), __fmul_rn(dy, dy));
        float d  = __fsqrt_rn(dd);
        float v  = __fadd_rn(__fsub_rn(__fdiv_rn(__fmul_rn(d, 40000000.0f),
                                                 1572.0f),
                                       113.0f),
                             1.0f);
        int t = (int)rintf(v);
        t = max(0, min(t, NTT-1));
        const float* sp = sig + (size_t)t * SS + s;
#pragma unroll
        for (int b = 0; b < BB; b++)
            acc[b] += __ldg(sp + (size_t)b * NTT * SS);
    }
#pragma unroll
    for (int b = 0; b < BB; b++)
        g_rec[(size_t)b * PIX + idx] = acc[b] * (1.0f / 32.0f);
}

// ---------------- global min/max ----------------
__device__ void atomicMinF(float* a, float v) {
    int old = __float_as_int(*a);
    while (v < __int_as_float(old)) {
        int prev = atomicCAS((int*)a, old, __float_as_int(v));
        if (prev == old) break;
        old = prev;
    }
}
__device__ void atomicMaxF(float* a, float v) {
    int old = __float_as_int(*a);
    while (v > __int_as_float(old)) {
        int prev = atomicCAS((int*)a, old, __float_as_int(v));
        if (prev == old) break;
        old = prev;
    }
}
__global__ void k_minmax_init() { g_mm[0] = INFINITY; g_mm[1] = -INFINITY; }

__global__ void k_minmax_reduce()
{
    float mn = INFINITY, mx = -INFINITY;
    for (int i = blockIdx.x * blockDim.x + threadIdx.x; i < IMG; i += gridDim.x * blockDim.x) {
        float v = g_rec[i];
        mn = fminf(mn, v);
        mx = fmaxf(mx, v);
    }
    __shared__ float smn[256], smx[256];
    int t = threadIdx.x;
    smn[t] = mn; smx[t] = mx;
    __syncthreads();
    for (int o = 128; o > 0; o >>= 1) {
        if (t < o) { smn[t] = fminf(smn[t], smn[t+o]); smx[t] = fmaxf(smx[t], smx[t+o]); }
        __syncthreads();
    }
    if (t == 0) { atomicMinF(&g_mm[0], smn[0]); atomicMaxF(&g_mm[1], smx[0]); }
}

__global__ void k_normalize(float* __restrict__ out_rec, int copy_out)
{
    int i = blockIdx.x * blockDim.x + threadIdx.x;
    if (i >= IMG) return;
    float mn = g_mm[0], mx = g_mm[1];
    float v = __fdiv_rn(__fsub_rn(g_rec[i], mn), __fsub_rn(mx, mn));
    g_rec[i] = v;
    if (copy_out) out_rec[i] = v;
}

// =====================================================================
// conv stride-2 k4 p1 — implicit GEMM v3 (3xTF32 tensor cores)
// 64x64 tile, 256 threads (8 warps, 4x2 warp grid of 16x32 sub-tiles),
// staging identical to v1.5; operands Dekker-split into tf32 hi/lo
// planes; inner loop = mma.m16n8k8 with hi*lo + lo*hi + hi*hi.
// =====================================================================
template<int Cin, int Hi, int Wi, int Cout, int ACT>
__device__ __forceinline__ void conv_v3(const float* __restrict__ in,
                                        const float* __restrict__ w,
                                        float* __restrict__ out)
{
    constexpr int Ho = Hi >> 1, Wo = Wi >> 1;
    constexpr int HoWo = Ho * Wo;
    constexpr int HiWi = Hi * Wi;
    const int m0 = blockIdx.y * 64;
    const int p0 = blockIdx.x * 64;

    __shared__ __align__(16) float AsH[2][16][72], AsL[2][16][72];
    __shared__ __align__(16) float BsH[2][16][72], BsL[2][16][72];

    const int tid  = threadIdx.x;
    const int kk   = tid & 15;      // staging tap index
    const int rowq = tid >> 4;      // staging row group
    const int ky = kk >> 2, kx = kk & 3;

    const int wid  = tid >> 5;      // 0..7
    const int lane = tid & 31;
    const int wm   = wid & 3;       // m sub-tile: 16*wm
    const int wn   = wid >> 2;      // n sub-tile: 32*wn
    const int grp  = lane >> 2;     // 0..7
    const int qd   = lane & 3;      // 0..3

    int woff[4], bofs[4];
#pragma unroll
    for (int q = 0; q < 4; q++) {
        int n = rowq + 16 * q;
        woff[q] = (m0 + n) * Cin * 16 + kk;
        int p = p0 + n;
        int b = p / HoWo; int r = p - b * HoWo;
        int y = r / Wo;   int x = r - y * Wo;
        int iy = 2*y - 1 + ky, ix = 2*x - 1 + kx;
        bool v = iy >= 0 && iy < Hi && ix >= 0 && ix < Wi;
        bofs[q] = v ? (b * Cin * HiWi + iy * Wi + ix) : -1;
    }

    float aR[4], bR[4];
    // prologue: stage chunk 0
#pragma unroll
    for (int q = 0; q < 4; q++) {
        aR[q] = __ldg(w + woff[q]);
        float v = 0.f;
        if (bofs[q] >= 0) {
            v = __ldg(in + bofs[q]);
            if (ACT) v = (v >= 0.f) ? v : 0.2f * v;
        }
        bR[q] = v;
    }
#pragma unroll
    for (int q = 0; q < 4; q++) {
        int col = rowq + 16 * q;
        float ah = tf32f(aR[q]);
        AsH[0][kk][col] = ah;
        AsL[0][kk][col] = tf32f(aR[q] - ah);
        float bh = tf32f(bR[q]);
        BsH[0][kk][col] = bh;
        BsL[0][kk][col] = tf32f(bR[q] - bh);
    }
    __syncthreads();

    float acc[4][4];
#pragma unroll
    for (int t = 0; t < 4; t++)
#pragma unroll
        for (int j = 0; j < 4; j++) acc[t][j] = 0.f;

    int buf = 0;
    for (int cci = 0; cci < Cin; cci++) {
        const bool more = (cci + 1 < Cin);
        if (more) {
            const float* wp = w + (size_t)(cci + 1) * 16;
            const float* ip = in + (size_t)(cci + 1) * HiWi;
#pragma unroll
            for (int q = 0; q < 4; q++) {
                aR[q] = __ldg(wp + woff[q]);
                float v = 0.f;
                if (bofs[q] >= 0) {
                    v = __ldg(ip + bofs[q]);
                    if (ACT) v = (v >= 0.f) ? v : 0.2f * v;
                }
                bR[q] = v;
            }
        }
        // compute: 2 k-steps of 8
#pragma unroll
        for (int ks = 0; ks < 2; ks++) {
            int k0 = 8 * ks;
            int mrow = 16 * wm + grp;
            unsigned aH[4], aL[4];
            aH[0] = __float_as_uint(AsH[buf][k0 + qd    ][mrow    ]);
            aH[1] = __float_as_uint(AsH[buf][k0 + qd    ][mrow + 8]);
            aH[2] = __float_as_uint(AsH[buf][k0 + qd + 4][mrow    ]);
            aH[3] = __float_as_uint(AsH[buf][k0 + qd + 4][mrow + 8]);
            aL[0] = __float_as_uint(AsL[buf][k0 + qd    ][mrow    ]);
            aL[1] = __float_as_uint(AsL[buf][k0 + qd    ][mrow + 8]);
            aL[2] = __float_as_uint(AsL[buf][k0 + qd + 4][mrow    ]);
            aL[3] = __float_as_uint(AsL[buf][k0 + qd + 4][mrow + 8]);
#pragma unroll
            for (int t = 0; t < 4; t++) {
                int nc = 32 * wn + 8 * t + grp;
                unsigned bH0 = __float_as_uint(BsH[buf][k0 + qd    ][nc]);
                unsigned bH1 = __float_as_uint(BsH[buf][k0 + qd + 4][nc]);
                unsigned bL0 = __float_as_uint(BsL[buf][k0 + qd    ][nc]);
                unsigned bL1 = __float_as_uint(BsL[buf][k0 + qd + 4][nc]);
                mma_tf32(acc[t], aH, bL0, bL1);
                mma_tf32(acc[t], aL, bH0, bH1);
                mma_tf32(acc[t], aH, bH0, bH1);
            }
        }
        if (more) {
            int nb = buf ^ 1;
#pragma unroll
            for (int q = 0; q < 4; q++) {
                int col = rowq + 16 * q;
                float ah = tf32f(aR[q]);
                AsH[nb][kk][col] = ah;
                AsL[nb][kk][col] = tf32f(aR[q] - ah);
                float bh = tf32f(bR[q]);
                BsH[nb][kk][col] = bh;
                BsL[nb][kk][col] = tf32f(bR[q] - bh);
            }
            __syncthreads();
            buf = nb;
        }
    }

    // epilogue: c0/c1 are n-contiguous pairs -> float2 stores
#pragma unroll
    for (int t = 0; t < 4; t++) {
        int p = p0 + 32 * wn + 8 * t + 2 * qd;
        int b = p / HoWo; int r = p - b * HoWo;
        int m1 = m0 + 16 * wm + grp;
        float2 v0 = make_float2(acc[t][0], acc[t][1]);
        float2 v1 = make_float2(acc[t][2], acc[t][3]);
        *(float2*)(&out[(size_t)(b * Cout + m1    ) * HoWo + r]) = v0;
        *(float2*)(&out[(size_t)(b * Cout + m1 + 8) * HoWo + r]) = v1;
    }
}

__global__ void __launch_bounds__(256,2) k_conv_d0(const float* __restrict__ w)
{ conv_v3<1,256,256,64,0>(g_rec, w, g_h0); }
__global__ void __launch_bounds__(256,2) k_conv_d1(const float* __restrict__ w)
{ conv_v3<64,128,128,128,1>(g_h0, w, g_h1); }
__global__ void __launch_bounds__(256,2) k_conv_d2(const float* __restrict__ w)
{ conv_v3<128,64,64,256,1>(g_h1, w, g_h2); }
__global__ void __launch_bounds__(256,2) k_conv_d3(const float* __restrict__ w)
{ conv_v3<256,32,32,512,1>(g_h2, w, g_h3); }
__global__ void __launch_bounds__(256,2) k_conv_d4(const float* __restrict__ w)
{ conv_v3<512,16,16,512,1>(g_h3, w, g_h4); }

// ---------------- deconv weight repack (per-parity) ----------------
__global__ void k_repack(const float* __restrict__ w, int Cin, int Cout)
{
    int idx = blockIdx.x * blockDim.x + threadIdx.x;
    int total = 4 * Cout * Cin * 4;
    if (idx >= total) return;
    int t  = idx & 3;
    int tmp = idx >> 2;
    int ci = tmp % Cin; tmp /= Cin;
    int m  = tmp % Cout;
    int pz = tmp / Cout;
    int py = pz >> 1, px = pz & 1;
    int di = t >> 1,  dj = t & 1;
    int ky = py ? (1 + 2*di) : (2*di);
    int kx = px ? (1 + 2*dj) : (2*dj);
    g_wpack[idx] = w[(((size_t)ci * Cout + m) * 4 + (3 - ky)) * 4 + (3 - kx)];
}

// =====================================================================
// transposed conv stride-2 k4 p2 — parity implicit GEMM v3 (3xTF32)
// =====================================================================
template<int Cin, int C1, int Hi, int Wi, int Cout>
__device__ __forceinline__ void deconv_v3(const float* __restrict__ in1,
                                          const float* __restrict__ in2,
                                          float* __restrict__ out)
{
    constexpr int HiWi = Hi * Wi;
    constexpr int Wo = 2 * Wi;
    constexpr int HoWo = 4 * HiWi;
    constexpr int C2 = Cin - C1;
    constexpr int NCH = Cin / 4;
    const int pz = blockIdx.z;
    const int py = pz >> 1, px = pz & 1;
    const int m0 = blockIdx.y * 64;
    const int n0 = blockIdx.x * 64;

    __shared__ __align__(16) float AsH[2][16][72], AsL[2][16][72];
    __shared__ __align__(16) float BsH[2][16][72], BsL[2][16][72];

    const int tid  = threadIdx.x;
    const int kk   = tid & 15;      // cil*4 + t
    const int rowq = tid >> 4;
    const int cil = kk >> 2, tt = kk & 3;
    const int di = tt >> 1, dj = tt & 1;

    const int wid  = tid >> 5;
    const int lane = tid & 31;
    const int wm   = wid & 3;
    const int wn   = wid >> 2;
    const int grp  = lane >> 2;
    const int qd   = lane & 3;

    int woff[4], pixq[4], bq[4];
#pragma unroll
    for (int q = 0; q < 4; q++) {
        int n = n0 + rowq + 16 * q;
        int b = n / HiWi; int r = n - b * HiWi;
        int yy = r / Wi;  int xx = r - yy * Wi;
        int i = py ? (yy + di) : (yy - 1 + di);
        int j = px ? (xx + dj) : (xx - 1 + dj);
        bool v = i >= 0 && i < Hi && j >= 0 && j < Wi;
        pixq[q] = v ? (i * Wi + j) : -1;
        bq[q] = b;
        int m = m0 + rowq + 16 * q;
        woff[q] = ((pz * Cout + m) * Cin + cil) * 4 + tt;
    }

    float aR[4], bR[4];
    // prologue: chunk 0 (ci = cil)
#pragma unroll
    for (int q = 0; q < 4; q++) {
        aR[q] = g_wpack[woff[q]];
        float v = 0.f;
        if (pixq[q] >= 0) {
            const float* src = (cil < C1)
                ? in1 + (size_t)(bq[q] * C1 + cil) * HiWi
                : in2 + (size_t)(bq[q] * C2 + (cil - C1)) * HiWi;
            v = fmaxf(__ldg(src + pixq[q]), 0.f);
        }
        bR[q] = v;
    }
#pragma unroll
    for (int q = 0; q < 4; q++) {
        int col = rowq + 16 * q;
        float ah = tf32f(aR[q]);
        AsH[0][kk][col] = ah;
        AsL[0][kk][col] = tf32f(aR[q] - ah);
        float bh = tf32f(bR[q]);
        BsH[0][kk][col] = bh;
        BsL[0][kk][col] = tf32f(bR[q] - bh);
    }
    __syncthreads();

    float acc[4][4];
#pragma unroll
    for (int t = 0; t < 4; t++)
#pragma unroll
        for (int j = 0; j < 4; j++) acc[t][j] = 0.f;

    int buf = 0;
    for (int s = 0; s < NCH; s++) {
        const bool more = (s + 1 < NCH);
        if (more) {
            int ci = 4 * (s + 1) + cil;
#pragma unroll
            for (int q = 0; q < 4; q++) {
                aR[q] = g_wpack[woff[q] + (s + 1) * 16];
                float v = 0.f;
                if (pixq[q] >= 0) {
                    const float* src = (ci < C1)
                        ? in1 + (size_t)(bq[q] * C1 + ci) * HiWi
                        : in2 + (size_t)(bq[q] * C2 + (ci - C1)) * HiWi;
                    v = fmaxf(__ldg(src + pixq[q]), 0.f);
                }
                bR[q] = v;
            }
        }
#pragma unroll
        for (int ks = 0; ks < 2; ks++) {
            int k0 = 8 * ks;
            int mrow = 16 * wm + grp;
            unsigned aH[4], aL[4];
            aH[0] = __float_as_uint(AsH[buf][k0 + qd    ][mrow    ]);
            aH[1] = __float_as_uint(AsH[buf][k0 + qd    ][mrow + 8]);
            aH[2] = __float_as_uint(AsH[buf][k0 + qd + 4][mrow    ]);
            aH[3] = __float_as_uint(AsH[buf][k0 + qd + 4][mrow + 8]);
            aL[0] = __float_as_uint(AsL[buf][k0 + qd    ][mrow    ]);
            aL[1] = __float_as_uint(AsL[buf][k0 + qd    ][mrow + 8]);
            aL[2] = __float_as_uint(AsL[buf][k0 + qd + 4][mrow    ]);
            aL[3] = __float_as_uint(AsL[buf][k0 + qd + 4][mrow + 8]);
#pragma unroll
            for (int t = 0; t < 4; t++) {
                int nc = 32 * wn + 8 * t + grp;
                unsigned bH0 = __float_as_uint(BsH[buf][k0 + qd    ][nc]);
                unsigned bH1 = __float_as_uint(BsH[buf][k0 + qd + 4][nc]);
                unsigned bL0 = __float_as_uint(BsL[buf][k0 + qd    ][nc]);
                unsigned bL1 = __float_as_uint(BsL[buf][k0 + qd + 4][nc]);
                mma_tf32(acc[t], aH, bL0, bL1);
                mma_tf32(acc[t], aL, bH0, bH1);
                mma_tf32(acc[t], aH, bH0, bH1);
            }
        }
        if (more) {
            int nb = buf ^ 1;
#pragma unroll
            for (int q = 0; q < 4; q++) {
                int col = rowq + 16 * q;
                float ah = tf32f(aR[q]);
                AsH[nb][kk][col] = ah;
                AsL[nb][kk][col] = tf32f(aR[q] - ah);
                float bh = tf32f(bR[q]);
                BsH[nb][kk][col] = bh;
                BsL[nb][kk][col] = tf32f(bR[q] - bh);
            }
            __syncthreads();
            buf = nb;
        }
    }

    // epilogue: scatter by parity (scalar stores)
#pragma unroll
    for (int t = 0; t < 4; t++) {
#pragma unroll
        for (int half = 0; half < 2; half++) {
            int n = n0 + 32 * wn + 8 * t + 2 * qd + half;
            int b = n / HiWi; int r = n - b * HiWi;
            int yy = r / Wi;  int xx = r - yy * Wi;
            int y = 2 * yy + py, x = 2 * xx + px;
            int m1 = m0 + 16 * wm + grp;
            out[(size_t)(b * Cout + m1    ) * HoWo + y * Wo + x] = acc[t][half];
            out[(size_t)(b * Cout + m1 + 8) * HoWo + y * Wo + x] = acc[t][2 + half];
        }
    }
}

__global__ void __launch_bounds__(256,2) k_deconv_u4()
{ deconv_v3<512,512,8,8,512>(g_h4, g_h4, g_u4); }
__global__ void __launch_bounds__(256,2) k_deconv_u3()
{ deconv_v3<1024,512,16,16,256>(g_h3, g_u4, g_u3); }
__global__ void __launch_bounds__(256,2) k_deconv_u2()
{ deconv_v3<512,256,32,32,128>(g_h2, g_u3, g_u2); }
__global__ void __launch_bounds__(256,2) k_deconv_u1()
{ deconv_v3<256,128,64,64,64>(g_h1, g_u2, g_u1); }

// ---------------- batchnorm ----------------
template<int C, int HW>
__device__ __forceinline__ void bn_stats_body(const float* __restrict__ x,
                                              const float* __restrict__ g,
                                              const float* __restrict__ bet)
{
    int c = blockIdx.x;
    constexpr int per = BB * HW;
    double s = 0.0, s2 = 0.0;
    for (int i = threadIdx.x; i < per; i += blockDim.x) {
        int bb = i / HW; int r = i - bb * HW;
        float v = x[(size_t)(bb * C + c) * HW + r];
        s  += v;
        s2 += (double)v * (double)v;
    }
    __shared__ double sh1[256], sh2[256];
    int tidl = threadIdx.x;
    sh1[tidl] = s; sh2[tidl] = s2;
    __syncthreads();
    for (int o = 128; o > 0; o >>= 1) {
        if (tidl < o) { sh1[tidl] += sh1[tidl+o]; sh2[tidl] += sh2[tidl+o]; }
        __syncthreads();
    }
    if (tidl == 0) {
        double m   = sh1[0] / per;
        double var = sh2[0] / per - m * m;
        float sc = g[c] * (float)(1.0 / sqrt(var + 1e-5));
        g_scale[c] = sc;
        g_shift[c] = bet[c] - (float)m * sc;
    }
}

template<int C, int HW>
__device__ __forceinline__ void bn_apply_body(float* __restrict__ x)
{
    constexpr int total = BB * C * HW;
    int i = blockIdx.x * blockDim.x + threadIdx.x;
    if (i >= total) return;
    int c = (i / HW) % C;
    x[i] = x[i] * g_scale[c] + g_shift[c];
}

__global__ void k_bns_h1(const float* g, const float* b){ bn_stats_body<128,4096>(g_h1,g,b); }
__global__ void k_bna_h1(){ bn_apply_body<128,4096>(g_h1); }
__global__ void k_bns_h2(const float* g, const float* b){ bn_stats_body<256,1024>(g_h2,g,b); }
__global__ void k_bna_h2(){ bn_apply_body<256,1024>(g_h2); }
__global__ void k_bns_h3(const float* g, const float* b){ bn_stats_body<512,256>(g_h3,g,b); }
__global__ void k_bna_h3(){ bn_apply_body<512,256>(g_h3); }
__global__ void k_bns_u4(const float* g, const float* b){ bn_stats_body<512,256>(g_u4,g,b); }
__global__ void k_bna_u4(){ bn_apply_body<512,256>(g_u4); }
__global__ void k_bns_u3(const float* g, const float* b){ bn_stats_body<256,1024>(g_u3,g,b); }
__global__ void k_bna_u3(){ bn_apply_body<256,1024>(g_u3); }
__global__ void k_bns_u2(const float* g, const float* b){ bn_stats_body<128,4096>(g_u2,g,b); }
__global__ void k_bna_u2(){ bn_apply_body<128,4096>(g_u2); }
__global__ void k_bns_u1(const float* g, const float* b){ bn_stats_body<64,16384>(g_u1,g,b); }
__global__ void k_bna_u1(){ bn_apply_body<64,16384>(g_u1); }

// ---------------- final deconv u0: 2x2 output quad per thread ----------------
__global__ void k_deconv_u0(const float* __restrict__ w,     // (128,1,4,4)
                            const float* __restrict__ b0,
                            float* __restrict__ out)         // (16,1,256,256)
{
    __shared__ float ws[2048];
    for (int i = threadIdx.x; i < 2048; i += blockDim.x) ws[i] = w[i];
    __syncthreads();

    int idx = blockIdx.x * blockDim.x + threadIdx.x;   // over BB*128*128
    if (idx >= BB * 128 * 128) return;
    int xx = idx & 127;
    int yy = (idx >> 7) & 127;
    int b  = idx >> 14;

    const float* h0p = g_h0 + (size_t)b * 64 * 16384;
    const float* u1p = g_u1 + (size_t)b * 64 * 16384;

    float a00 = 0.f, a01 = 0.f, a10 = 0.f, a11 = 0.f;

    for (int ci = 0; ci < 128; ci++) {
        const float* src = (ci < 64) ? (h0p + ci * 16384)
                                     : (u1p + (ci - 64) * 16384);
        float v[3][3];
#pragma unroll
        for (int dy = 0; dy < 3; dy++) {
            int i = yy - 1 + dy;
#pragma unroll
            for (int dxx = 0; dxx < 3; dxx++) {
                int jx = xx - 1 + dxx;
                v[dy][dxx] = (i >= 0 && i < 128 && jx >= 0 && jx < 128)
                             ? fmaxf(__ldg(src + i * 128 + jx), 0.f) : 0.f;
            }
        }
        const float* wsr = ws + ci * 16;
#pragma unroll
        for (int di = 0; di < 2; di++)
#pragma unroll
            for (int dj = 0; dj < 2; dj++)
                a00 += v[di][dj] * wsr[(3 - 2*di) * 4 + (3 - 2*dj)];
#pragma unroll
        for (int di = 0; di < 2; di++)
#pragma unroll
            for (int dj = 0; dj < 2; dj++)
                a01 += v[di][dj+1] * wsr[(3 - 2*di) * 4 + (2 - 2*dj)];
#pragma unroll
        for (int di = 0; di < 2; di++)
#pragma unroll
            for (int dj = 0; dj < 2; dj++)
                a10 += v[di+1][dj] * wsr[(2 - 2*di) * 4 + (3 - 2*dj)];
#pragma unroll
        for (int di = 0; di < 2; di++)
#pragma unroll
            for (int dj = 0; dj < 2; dj++)
                a11 += v[di+1][dj+1] * wsr[(2 - 2*di) * 4 + (2 - 2*dj)];
    }

    float bias = __ldg(&b0[0]);
    int base = b * PIX + (2 * yy) * 256 + 2 * xx;
    out[base]       = 1.0f / (1.0f + expf(-(a00 + bias)));
    out[base + 1]   = 1.0f / (1.0f + expf(-(a01 + bias)));
    out[base + 256] = 1.0f / (1.0f + expf(-(a10 + bias)));
    out[base + 257] = 1.0f / (1.0f + expf(-(a11 + bias)));
}

// ---------------- driver ----------------
extern "C" void kernel_launch(void* const* d_in, const int* in_sizes, int n_in,
                              void* d_out, int out_size)
{
    const float* sig   = (const float*)d_in[0];
    const float* trans = (const float*)d_in[1];
    const float* w_d0  = (const float*)d_in[2];
    const float* w_d1  = (const float*)d_in[3];
    const float* g_d1  = (const float*)d_in[4];
    const float* b_d1  = (const float*)d_in[5];
    const float* w_d2  = (const float*)d_in[6];
    const float* g_d2  = (const float*)d_in[7];
    const float* b_d2  = (const float*)d_in[8];
    const float* w_d3  = (const float*)d_in[9];
    const float* g_d3  = (const float*)d_in[10];
    const float* b_d3  = (const float*)d_in[11];
    const float* w_d4  = (const float*)d_in[12];
    const float* w_u4  = (const float*)d_in[13];
    const float* g_u4p = (const float*)d_in[14];
    const float* b_u4p = (const float*)d_in[15];
    const float* w_u3  = (const float*)d_in[16];
    const float* g_u3p = (const float*)d_in[17];
    const float* b_u3p = (const float*)d_in[18];
    const float* w_u2  = (const float*)d_in[19];
    const float* g_u2p = (const float*)d_in[20];
    const float* b_u2p = (const float*)d_in[21];
    const float* w_u1  = (const float*)d_in[22];
    const float* g_u1p = (const float*)d_in[23];
    const float* b_u1p = (const float*)d_in[24];
    const float* w_u0  = (const float*)d_in[25];
    const float* b_u0  = (const float*)d_in[26];

    float* outp = (float*)d_out;
    float* out_rec = outp + IMG;
    int copy_rec = (out_size >= 2 * IMG) ? 1 : 0;

    // 1. backprojection + normalization (rec)
    k_backproject<<<PIX / 256, 256>>>(sig, trans);
    k_minmax_init<<<1, 1>>>();
    k_minmax_reduce<<<256, 256>>>();
    k_normalize<<<(IMG + 255) / 256, 256>>>(out_rec, copy_rec);

    // 2. encoder (grid: x = Ptot/64, y = Cout/64; 256 threads)
    k_conv_d0<<<dim3(4096, 1), 256>>>(w_d0);
    k_conv_d1<<<dim3(1024, 2), 256>>>(w_d1);
    k_bns_h1<<<128, 256>>>(g_d1, b_d1);
    k_bna_h1<<<BB*128*4096/256, 256>>>();
    k_conv_d2<<<dim3(256,  4), 256>>>(w_d2);
    k_bns_h2<<<256, 256>>>(g_d2, b_d2);
    k_bna_h2<<<BB*256*1024/256, 256>>>();
    k_conv_d3<<<dim3(64,   8), 256>>>(w_d3);
    k_bns_h3<<<512, 256>>>(g_d3, b_d3);
    k_bna_h3<<<BB*512*256/256, 256>>>();
    k_conv_d4<<<dim3(16,   8), 256>>>(w_d4);

    // 3. decoder (grid: x = Ncls/64, y = Cout/64, z = parity; 256 threads)
    k_repack<<<(512*512*16 + 255)/256, 256>>>(w_u4, 512, 512);
    k_deconv_u4<<<dim3(16,  8, 4), 256>>>();
    k_bns_u4<<<512, 256>>>(g_u4p, b_u4p);
    k_bna_u4<<<BB*512*256/256, 256>>>();

    k_repack<<<(1024*256*16 + 255)/256, 256>>>(w_u3, 1024, 256);
    k_deconv_u3<<<dim3(64,  4, 4), 256>>>();
    k_bns_u3<<<256, 256>>>(g_u3p, b_u3p);
    k_bna_u3<<<BB*256*1024/256, 256>>>();

    k_repack<<<(512*128*16 + 255)/256, 256>>>(w_u2, 512, 128);
    k_deconv_u2<<<dim3(256, 2, 4), 256>>>();
    k_bns_u2<<<128, 256>>>(g_u2p, b_u2p);
    k_bna_u2<<<BB*128*4096/256, 256>>>();

    k_repack<<<(256*64*16 + 255)/256, 256>>>(w_u1, 256, 64);
    k_deconv_u1<<<dim3(1024, 1, 4), 256>>>();
    k_bns_u1<<<64, 256>>>(g_u1p, b_u1p);
    k_bna_u1<<<BB*64*16384/256, 256>>>();

    // 4. final layer: 2x2 quad per thread, fused bias + sigmoid
    k_deconv_u0<<<(BB*128*128 + 255) / 256, 256>>>(w_u0, b_u0, outp);
}

// round 11
// speedup vs baseline: 1.0343x; 1.0293x over previous
#include <cuda_runtime.h>
#include <math.h>

#define BB   16
#define SS   32
#define NTT  2029
#define NN   256
#define PIX  (NN*NN)
#define IMG  (BB*PIX)

__device__ float g_rec [BB*PIX];
__device__ float g_h0  [BB*64 *128*128];
__device__ float g_h1  [BB*128*64 *64 ];
__device__ float g_h2  [BB*256*32 *32 ];
__device__ float g_h3  [BB*512*16 *16 ];
__device__ float g_h4  [BB*512*8  *8  ];
__device__ float g_u4  [BB*512*16 *16 ];
__device__ float g_u3  [BB*256*32 *32 ];
__device__ float g_u2  [BB*128*64 *64 ];
__device__ float g_u1  [BB*64 *128*128];
__device__ float g_wpack[4*512*512*4];
__device__ float g_mm[2];
__device__ float g_scale[512];
__device__ float g_shift[512];

__device__ __forceinline__ float tf32f(float x)
{ unsigned r; asm("cvt.rna.tf32.f32 %0, %1;" : "=r"(r) : "f"(x)); return __uint_as_float(r); }

__device__ __forceinline__ void mma4(float* c, float4 a, float2 b)
{
    asm("mma.sync.aligned.m16n8k8.row.col.f32.tf32.tf32.f32 "
        "{%0,%1,%2,%3}, {%4,%5,%6,%7}, {%8,%9}, {%0,%1,%2,%3};"
        : "+f"(c[0]), "+f"(c[1]), "+f"(c[2]), "+f"(c[3])
        : "r"(__float_as_uint(a.x)), "r"(__float_as_uint(a.y)),
          "r"(__float_as_uint(a.z)), "r"(__float_as_uint(a.w)),
          "r"(__float_as_uint(b.x)), "r"(__float_as_uint(b.y)));
}

// ---------------- backprojection (bit-exact passing form) ----------------
__global__ void k_backproject(const float* __restrict__ sig,
                              const float* __restrict__ trans)
{
    int idx = blockIdx.x * blockDim.x + threadIdx.x;
    if (idx >= PIX) return;
    int j = idx & 255, i = idx >> 8;
    const float startf = -0.0125f, stopf = 0.0125f;
    float stepj = __fdiv_rn((float)j, 255.0f);
    float stepi = __fdiv_rn((float)i, 255.0f);
    float cj = __fadd_rn(__fmul_rn(startf, __fsub_rn(1.0f, stepj)), __fmul_rn(stopf, stepj));
    float ci = __fadd_rn(__fmul_rn(startf, __fsub_rn(1.0f, stepi)), __fmul_rn(stopf, stepi));
    float acc[BB];
#pragma unroll
    for (int b = 0; b < BB; b++) acc[b] = 0.f;
    for (int s = 0; s < SS; s++) {
        float dx = __fsub_rn(cj, __ldg(&trans[2*s+0]));
        float dy = __fsub_rn(ci, __ldg(&trans[2*s+1]));
        float dd = __fadd_rn(__fmul_rn(dx, dx), __fmul_rn(dy, dy));
        float d  = __fsqrt_rn(dd);
        float v  = __fadd_rn(__fsub_rn(__fdiv_rn(__fmul_rn(d, 40000000.0f), 1572.0f), 113.0f), 1.0f);
        int t = (int)rintf(v);
        t = max(0, min(t, NTT-1));
        const float* sp = sig + (size_t)t * SS + s;
#pragma unroll
        for (int b = 0; b < BB; b++) acc[b] += __ldg(sp + (size_t)b * NTT * SS);
    }
#pragma unroll
    for (int b = 0; b < BB; b++) g_rec[(size_t)b * PIX + idx] = acc[b] * (1.0f / 32.0f);
}

__device__ void atomicMinF(float* a, float v) {
    int old = __float_as_int(*a);
    while (v < __int_as_float(old)) {
        int prev = atomicCAS((int*)a, old, __float_as_int(v));
        if (prev == old) break; old = prev;
    }
}
__device__ void atomicMaxF(float* a, float v) {
    int old = __float_as_int(*a);
    while (v > __int_as_float(old)) {
        int prev = atomicCAS((int*)a, old, __float_as_int(v));
        if (prev == old) break; old = prev;
    }
}
__global__ void k_minmax_init() { g_mm[0] = INFINITY; g_mm[1] = -INFINITY; }

__global__ void k_minmax_reduce()
{
    float mn = INFINITY, mx = -INFINITY;
    for (int i = blockIdx.x * blockDim.x + threadIdx.x; i < IMG; i += gridDim.x * blockDim.x) {
        float v = g_rec[i]; mn = fminf(mn, v); mx = fmaxf(mx, v);
    }
    __shared__ float smn[256], smx[256];
    int t = threadIdx.x;
    smn[t] = mn; smx[t] = mx;
    __syncthreads();
    for (int o = 128; o > 0; o >>= 1) {
        if (t < o) { smn[t] = fminf(smn[t], smn[t+o]); smx[t] = fmaxf(smx[t], smx[t+o]); }
        __syncthreads();
    }
    if (t == 0) { atomicMinF(&g_mm[0], smn[0]); atomicMaxF(&g_mm[1], smx[0]); }
}

__global__ void k_normalize(float* __restrict__ out_rec, int copy_out)
{
    int i = blockIdx.x * blockDim.x + threadIdx.x;
    if (i >= IMG) return;
    float mn = g_mm[0], mx = g_mm[1];
    float v = __fdiv_rn(__fsub_rn(g_rec[i], mn), __fsub_rn(mx, mn));
    g_rec[i] = v;
    if (copy_out) out_rec[i] = v;
}

// ---------------- conv d0 (Cin=1): direct, taps ascending ----------------
__global__ void __launch_bounds__(256) k_conv_d0(const float* __restrict__ w)
{
    __shared__ float ws[1024];
    for (int i = threadIdx.x; i < 1024; i += 256) ws[i] = w[i];
    __syncthreads();
    int idx = blockIdx.x * 256 + threadIdx.x;         // 16*128*128
    int x = idx & 127, y = (idx >> 7) & 127, b = idx >> 14;
    float patch[16];
#pragma unroll
    for (int t = 0; t < 16; t++) {
        int iy = 2*y - 1 + (t >> 2), ix = 2*x - 1 + (t & 3);
        patch[t] = (iy >= 0 && iy < 256 && ix >= 0 && ix < 256)
                   ? g_rec[b * PIX + iy * 256 + ix] : 0.f;
    }
    float* op = g_h0 + ((size_t)b * 64 << 14) + (y << 7) + x;
    for (int co = 0; co < 64; co++) {
        float a = 0.f;
#pragma unroll
        for (int t = 0; t < 16; t++) a += patch[t] * ws[co * 16 + t];
        op[(size_t)co << 14] = a;
    }
}

// =====================================================================
// conv stride-2 k4 p1 — v4: 3xTF32 mma, fragment-ordered smem, K-chunk 32
// 64x64 tile, 256 thr, 8 warps (wm=wid&3 -> 16 m-rows, wn=wid>>2 -> 32 n)
// =====================================================================
template<int Cin, int Hi, int Wi, int Cout, int ACT>
__device__ __forceinline__ void conv_v4(const float* __restrict__ in,
                                        const float* __restrict__ w,
                                        float* __restrict__ out)
{
    constexpr int Ho = Hi >> 1, Wo = Wi >> 1, HoWo = Ho * Wo, HiWi = Hi * Wi;
    constexpr int NCH = Cin / 2;              // 32-K chunks
    constexpr int AROW = 8 * Cin * 16;
    const int m0 = blockIdx.y * 64, p0 = blockIdx.x * 64;

    __shared__ float AF[2][4][4][128];        // [plane][k8][mblk][lane*4+r]
    __shared__ float BF[2][4][8][68];         // [plane][k8][nblk][lane*2+h]

    const int tid = threadIdx.x, lane = tid & 31, wid = tid >> 5;
    const int wm = wid & 3, wn = wid >> 2, grp = lane >> 2, qd = lane & 3;

    // A staging: 2 fragment quads per thread
    const float* aptr[2]; int aks[2], amf[2], aln[2];
#pragma unroll
    for (int u = 0; u < 2; u++) {
        int qid = 2 * tid + u;
        aks[u] = qid >> 7; amf[u] = (qid >> 5) & 3; aln[u] = qid & 31;
        int m = m0 + 16 * amf[u] + (aln[u] >> 2);
        aptr[u] = w + (size_t)m * Cin * 16 + 8 * aks[u] + (aln[u] & 3);
    }
    // B staging: 4 fragment pairs per thread
    const int ksb = tid >> 6, nbb = (tid >> 3) & 7, lnb = (tid & 7) * 4;
    const int cciL = ksb >> 1;
    int bofs[4][2];
#pragma unroll
    for (int j = 0; j < 4; j++) {
        int ln = lnb + j;
        int p = p0 + 8 * nbb + (ln >> 2);
        int b = p / HoWo, r = p - b * HoWo, y = r / Wo, x = r - y * Wo;
#pragma unroll
        for (int kh = 0; kh < 2; kh++) {
            int tap = (8 * ksb + (ln & 3) + 4 * kh) & 15;
            int iy = 2*y - 1 + (tap >> 2), ix = 2*x - 1 + (tap & 3);
            bool ok = iy >= 0 && iy < Hi && ix >= 0 && ix < Wi;
            bofs[j][kh] = ok ? (b * Cin * HiWi + iy * Wi + ix) : -1;
        }
    }

    float aV[2][4], bV[4][2];
    auto ldA = [&] {
#pragma unroll
        for (int u = 0; u < 2; u++) {
            aV[u][0] = __ldg(aptr[u]);     aV[u][1] = __ldg(aptr[u] + AROW);
            aV[u][2] = __ldg(aptr[u] + 4); aV[u][3] = __ldg(aptr[u] + AROW + 4);
            aptr[u] += 32;
        }
    };
    auto ldB = [&](int ch) {
        int co = (2 * ch + cciL) * HiWi;
#pragma unroll
        for (int j = 0; j < 4; j++)
#pragma unroll
            for (int kh = 0; kh < 2; kh++) {
                float v = 0.f;
                if (bofs[j][kh] >= 0) {
                    v = __ldg(in + bofs[j][kh] + co);
                    if (ACT) v = (v >= 0.f) ? v : 0.2f * v;
                }
                bV[j][kh] = v;
            }
    };
    auto stAB = [&] {
#pragma unroll
        for (int u = 0; u < 2; u++) {
            float4 h = make_float4(tf32f(aV[u][0]), tf32f(aV[u][1]),
                                   tf32f(aV[u][2]), tf32f(aV[u][3]));
            float4 l = make_float4(tf32f(aV[u][0]-h.x), tf32f(aV[u][1]-h.y),
                                   tf32f(aV[u][2]-h.z), tf32f(aV[u][3]-h.w));
            *(float4*)&AF[0][aks[u]][amf[u]][aln[u]*4] = h;
            *(float4*)&AF[1][aks[u]][amf[u]][aln[u]*4] = l;
        }
#pragma unroll
        for (int j = 0; j < 4; j++) {
            int ln = lnb + j;
            float h0 = tf32f(bV[j][0]), h1 = tf32f(bV[j][1]);
            *(float2*)&BF[0][ksb][nbb][ln*2] = make_float2(h0, h1);
            *(float2*)&BF[1][ksb][nbb][ln*2] =
                make_float2(tf32f(bV[j][0]-h0), tf32f(bV[j][1]-h1));
        }
    };

    ldA(); ldB(0); stAB();
    __syncthreads();

    float acc[4][4];
#pragma unroll
    for (int t = 0; t < 4; t++)
#pragma unroll
        for (int c = 0; c < 4; c++) acc[t][c] = 0.f;

    for (int ch = 0; ch < NCH; ch++) {
        const bool more = (ch + 1 < NCH);
        if (more) { ldA(); ldB(ch + 1); }
#pragma unroll
        for (int ks = 0; ks < 4; ks++) {
            float4 aH = *(float4*)&AF[0][ks][wm][lane*4];
            float4 aL = *(float4*)&AF[1][ks][wm][lane*4];
#pragma unroll
            for (int t = 0; t < 4; t++) {
                int nb = 4 * wn + t;
                float2 bH = *(float2*)&BF[0][ks][nb][lane*2];
                float2 bL = *(float2*)&BF[1][ks][nb][lane*2];
                mma4(acc[t], aH, bL);
                mma4(acc[t], aL, bH);
                mma4(acc[t], aH, bH);
            }
        }
        __syncthreads();
        if (more) { stAB(); __syncthreads(); }
    }

#pragma unroll
    for (int t = 0; t < 4; t++) {
        int p = p0 + 32 * wn + 8 * t + 2 * qd;
        int b = p / HoWo, r = p - b * HoWo;
        int m1 = m0 + 16 * wm + grp;
        *(float2*)&out[(size_t)(b * Cout + m1    ) * HoWo + r] = make_float2(acc[t][0], acc[t][1]);
        *(float2*)&out[(size_t)(b * Cout + m1 + 8) * HoWo + r] = make_float2(acc[t][2], acc[t][3]);
    }
}

__global__ void __launch_bounds__(256,2) k_conv_d1(const float* __restrict__ w)
{ conv_v4<64,128,128,128,1>(g_h0, w, g_h1); }
__global__ void __launch_bounds__(256,2) k_conv_d2(const float* __restrict__ w)
{ conv_v4<128,64,64,256,1>(g_h1, w, g_h2); }
__global__ void __launch_bounds__(256,2) k_conv_d3(const float* __restrict__ w)
{ conv_v4<256,32,32,512,1>(g_h2, w, g_h3); }
__global__ void __launch_bounds__(256,2) k_conv_d4(const float* __restrict__ w)
{ conv_v4<512,16,16,512,1>(g_h3, w, g_h4); }

// ---------------- deconv weight repack (per-parity) ----------------
__global__ void k_repack(const float* __restrict__ w, int Cin, int Cout)
{
    int idx = blockIdx.x * blockDim.x + threadIdx.x;
    int total = 4 * Cout * Cin * 4;
    if (idx >= total) return;
    int t = idx & 3, tmp = idx >> 2;
    int ci = tmp % Cin; tmp /= Cin;
    int m = tmp % Cout;
    int pz = tmp / Cout;
    int py = pz >> 1, px = pz & 1;
    int di = t >> 1, dj = t & 1;
    int ky = py ? (1 + 2*di) : (2*di);
    int kx = px ? (1 + 2*dj) : (2*dj);
    g_wpack[idx] = w[(((size_t)ci * Cout + m) * 4 + (3 - ky)) * 4 + (3 - kx)];
}

// =====================================================================
// transposed conv — v4 (3xTF32, parity classes, K-chunk 32 = 8 ci)
// =====================================================================
template<int Cin, int C1, int Hi, int Wi, int Cout>
__device__ __forceinline__ void deconv_v4(const float* __restrict__ in1,
                                          const float* __restrict__ in2,
                                          float* __restrict__ out)
{
    constexpr int HiWi = Hi * Wi, Wo = 2 * Wi, HoWo = 4 * HiWi;
    constexpr int C2 = Cin - C1, NCH = Cin / 8;
    constexpr int AROW = 8 * Cin * 4;
    const int pz = blockIdx.z, py = pz >> 1, px = pz & 1;
    const int m0 = blockIdx.y * 64, n0 = blockIdx.x * 64;

    __shared__ float AF[2][4][4][128];
    __shared__ float BF[2][4][8][68];

    const int tid = threadIdx.x, lane = tid & 31, wid = tid >> 5;
    const int wm = wid & 3, wn = wid >> 2, grp = lane >> 2, qd = lane & 3;

    const float* aptr[2]; int aks[2], amf[2], aln[2];
#pragma unroll
    for (int u = 0; u < 2; u++) {
        int qid = 2 * tid + u;
        aks[u] = qid >> 7; amf[u] = (qid >> 5) & 3; aln[u] = qid & 31;
        int m = m0 + 16 * amf[u] + (aln[u] >> 2);
        aptr[u] = g_wpack + (size_t)(pz * Cout + m) * Cin * 4 + 8 * aks[u] + (aln[u] & 3);
    }
    const int ksb = tid >> 6, nbb = (tid >> 3) & 7, lnb = (tid & 7) * 4;
    int pofs[4][2], cl[4][2], bq[4];
#pragma unroll
    for (int j = 0; j < 4; j++) {
        int ln = lnb + j;
        int n = n0 + 8 * nbb + (ln >> 2);
        int b = n / HiWi, r = n - b * HiWi, yy = r / Wi, xx = r - yy * Wi;
        bq[j] = b;
#pragma unroll
        for (int kh = 0; kh < 2; kh++) {
            int kl = 8 * ksb + (ln & 3) + 4 * kh;
            cl[j][kh] = kl >> 2;
            int t = kl & 3, di = t >> 1, dj = t & 1;
            int i  = py ? (yy + di) : (yy - 1 + di);
            int jx = px ? (xx + dj) : (xx - 1 + dj);
            bool ok = i >= 0 && i < Hi && jx >= 0 && jx < Wi;
            pofs[j][kh] = ok ? (i * Wi + jx) : -1;
        }
    }

    float aV[2][4], bV[4][2];
    auto ldA = [&] {
#pragma unroll
        for (int u = 0; u < 2; u++) {
            aV[u][0] = __ldg(aptr[u]);     aV[u][1] = __ldg(aptr[u] + AROW);
            aV[u][2] = __ldg(aptr[u] + 4); aV[u][3] = __ldg(aptr[u] + AROW + 4);
            aptr[u] += 32;
        }
    };
    auto ldB = [&](int ch) {
#pragma unroll
        for (int j = 0; j < 4; j++)
#pragma unroll
            for (int kh = 0; kh < 2; kh++) {
                float v = 0.f;
                if (pofs[j][kh] >= 0) {
                    int ci = 8 * ch + cl[j][kh];
                    const float* s = (ci < C1)
                        ? in1 + (size_t)(bq[j] * C1 + ci) * HiWi
                        : in2 + (size_t)(bq[j] * C2 + (ci - C1)) * HiWi;
                    v = fmaxf(__ldg(s + pofs[j][kh]), 0.f);
                }
                bV[j][kh] = v;
            }
    };
    auto stAB = [&] {
#pragma unroll
        for (int u = 0; u < 2; u++) {
            float4 h = make_float4(tf32f(aV[u][0]), tf32f(aV[u][1]),
                                   tf32f(aV[u][2]), tf32f(aV[u][3]));
            float4 l = make_float4(tf32f(aV[u][0]-h.x), tf32f(aV[u][1]-h.y),
                                   tf32f(aV[u][2]-h.z), tf32f(aV[u][3]-h.w));
            *(float4*)&AF[0][aks[u]][amf[u]][aln[u]*4] = h;
            *(float4*)&AF[1][aks[u]][amf[u]][aln[u]*4] = l;
        }
#pragma unroll
        for (int j = 0; j < 4; j++) {
            int ln = lnb + j;
            float h0 = tf32f(bV[j][0]), h1 = tf32f(bV[j][1]);
            *(float2*)&BF[0][ksb][nbb][ln*2] = make_float2(h0, h1);
            *(float2*)&BF[1][ksb][nbb][ln*2] =
                make_float2(tf32f(bV[j][0]-h0), tf32f(bV[j][1]-h1));
        }
    };

    ldA(); ldB(0); stAB();
    __syncthreads();

    float acc[4][4];
#pragma unroll
    for (int t = 0; t < 4; t++)
#pragma unroll
        for (int c = 0; c < 4; c++) acc[t][c] = 0.f;

    for (int ch = 0; ch < NCH; ch++) {
        const bool more = (ch + 1 < NCH);
        if (more) { ldA(); ldB(ch + 1); }
#pragma unroll
        for (int ks = 0; ks < 4; ks++) {
            float4 aH = *(float4*)&AF[0][ks][wm][lane*4];
            float4 aL = *(float4*)&AF[1][ks][wm][lane*4];
#pragma unroll
            for (int t = 0; t < 4; t++) {
                int nb = 4 * wn + t;
                float2 bH = *(float2*)&BF[0][ks][nb][lane*2];
                float2 bL = *(float2*)&BF[1][ks][nb][lane*2];
                mma4(acc[t], aH, bL);
                mma4(acc[t], aL, bH);
                mma4(acc[t], aH, bH);
            }
        }
        __syncthreads();
        if (more) { stAB(); __syncthreads(); }
    }

#pragma unroll
    for (int t = 0; t < 4; t++) {
#pragma unroll
        for (int h = 0; h < 2; h++) {
            int n = n0 + 32 * wn + 8 * t + 2 * qd + h;
            int b = n / HiWi, r = n - b * HiWi;
            int yy = r / Wi, xx = r - yy * Wi;
            int y = 2 * yy + py, x = 2 * xx + px;
            int m1 = m0 + 16 * wm + grp;
            out[(size_t)(b * Cout + m1    ) * HoWo + y * Wo + x] = acc[t][h];
            out[(size_t)(b * Cout + m1 + 8) * HoWo + y * Wo + x] = acc[t][2 + h];
        }
    }
}

__global__ void __launch_bounds__(256,2) k_deconv_u4()
{ deconv_v4<512,512,8,8,512>(g_h4, g_h4, g_u4); }
__global__ void __launch_bounds__(256,2) k_deconv_u3()
{ deconv_v4<1024,512,16,16,256>(g_h3, g_u4, g_u3); }
__global__ void __launch_bounds__(256,2) k_deconv_u2()
{ deconv_v4<512,256,32,32,128>(g_h2, g_u3, g_u2); }
__global__ void __launch_bounds__(256,2) k_deconv_u1()
{ deconv_v4<256,128,64,64,64>(g_h1, g_u2, g_u1); }

// ---------------- batchnorm ----------------
template<int C, int HW>
__device__ __forceinline__ void bn_stats_body(const float* __restrict__ x,
                                              const float* __restrict__ g,
                                              const float* __restrict__ bet)
{
    int c = blockIdx.x;
    constexpr int per = BB * HW;
    double s = 0.0, s2 = 0.0;
    for (int i = threadIdx.x; i < per; i += blockDim.x) {
        int bb = i / HW; int r = i - bb * HW;
        float v = x[(size_t)(bb * C + c) * HW + r];
        s += v; s2 += (double)v * (double)v;
    }
    __shared__ double sh1[256], sh2[256];
    int tl = threadIdx.x;
    sh1[tl] = s; sh2[tl] = s2;
    __syncthreads();
    for (int o = 128; o > 0; o >>= 1) {
        if (tl < o) { sh1[tl] += sh1[tl+o]; sh2[tl] += sh2[tl+o]; }
        __syncthreads();
    }
    if (tl == 0) {
        double m = sh1[0] / per;
        double var = sh2[0] / per - m * m;
        float sc = g[c] * (float)(1.0 / sqrt(var + 1e-5));
        g_scale[c] = sc;
        g_shift[c] = bet[c] - (float)m * sc;
    }
}

template<int C, int HW>
__device__ __forceinline__ void bn_apply_body(float* __restrict__ x)
{
    constexpr int total = BB * C * HW;
    int i = blockIdx.x * blockDim.x + threadIdx.x;
    if (i >= total) return;
    int c = (i / HW) % C;
    x[i] = x[i] * g_scale[c] + g_shift[c];
}

__global__ void k_bns_h1(const float* g, const float* b){ bn_stats_body<128,4096>(g_h1,g,b); }
__global__ void k_bna_h1(){ bn_apply_body<128,4096>(g_h1); }
__global__ void k_bns_h2(const float* g, const float* b){ bn_stats_body<256,1024>(g_h2,g,b); }
__global__ void k_bna_h2(){ bn_apply_body<256,1024>(g_h2); }
__global__ void k_bns_h3(const float* g, const float* b){ bn_stats_body<512,256>(g_h3,g,b); }
__global__ void k_bna_h3(){ bn_apply_body<512,256>(g_h3); }
__global__ void k_bns_u4(const float* g, const float* b){ bn_stats_body<512,256>(g_u4,g,b); }
__global__ void k_bna_u4(){ bn_apply_body<512,256>(g_u4); }
__global__ void k_bns_u3(const float* g, const float* b){ bn_stats_body<256,1024>(g_u3,g,b); }
__global__ void k_bna_u3(){ bn_apply_body<256,1024>(g_u3); }
__global__ void k_bns_u2(const float* g, const float* b){ bn_stats_body<128,4096>(g_u2,g,b); }
__global__ void k_bna_u2(){ bn_apply_body<128,4096>(g_u2); }
__global__ void k_bns_u1(const float* g, const float* b){ bn_stats_body<64,16384>(g_u1,g,b); }
__global__ void k_bna_u1(){ bn_apply_body<64,16384>(g_u1); }

// ---------------- final deconv u0: 2x2 quad per thread ----------------
__global__ void k_deconv_u0(const float* __restrict__ w,
                            const float* __restrict__ b0,
                            float* __restrict__ out)
{
    __shared__ float ws[2048];
    for (int i = threadIdx.x; i < 2048; i += blockDim.x) ws[i] = w[i];
    __syncthreads();

    int idx = blockIdx.x * blockDim.x + threadIdx.x;
    if (idx >= BB * 128 * 128) return;
    int xx = idx & 127, yy = (idx >> 7) & 127, b = idx >> 14;

    const float* h0p = g_h0 + (size_t)b * 64 * 16384;
    const float* u1p = g_u1 + (size_t)b * 64 * 16384;
    float a00 = 0.f, a01 = 0.f, a10 = 0.f, a11 = 0.f;

    for (int ci = 0; ci < 128; ci++) {
        const float* src = (ci < 64) ? (h0p + ci * 16384) : (u1p + (ci - 64) * 16384);
        float v[3][3];
#pragma unroll
        for (int dy = 0; dy < 3; dy++) {
            int i = yy - 1 + dy;
#pragma unroll
            for (int dxx = 0; dxx < 3; dxx++) {
                int jx = xx - 1 + dxx;
                v[dy][dxx] = (i >= 0 && i < 128 && jx >= 0 && jx < 128)
                             ? fmaxf(__ldg(src + i * 128 + jx), 0.f) : 0.f;
            }
        }
        const float* wsr = ws + ci * 16;
#pragma unroll
        for (int di = 0; di < 2; di++)
#pragma unroll
            for (int dj = 0; dj < 2; dj++)
                a00 += v[di][dj] * wsr[(3 - 2*di) * 4 + (3 - 2*dj)];
#pragma unroll
        for (int di = 0; di < 2; di++)
#pragma unroll
            for (int dj = 0; dj < 2; dj++)
                a01 += v[di][dj+1] * wsr[(3 - 2*di) * 4 + (2 - 2*dj)];
#pragma unroll
        for (int di = 0; di < 2; di++)
#pragma unroll
            for (int dj = 0; dj < 2; dj++)
                a10 += v[di+1][dj] * wsr[(2 - 2*di) * 4 + (3 - 2*dj)];
#pragma unroll
        for (int di = 0; di < 2; di++)
#pragma unroll
            for (int dj = 0; dj < 2; dj++)
                a11 += v[di+1][dj+1] * wsr[(2 - 2*di) * 4 + (2 - 2*dj)];
    }

    float bias = __ldg(&b0[0]);
    int base = b * PIX + (2 * yy) * 256 + 2 * xx;
    out[base]       = 1.0f / (1.0f + expf(-(a00 + bias)));
    out[base + 1]   = 1.0f / (1.0f + expf(-(a01 + bias)));
    out[base + 256] = 1.0f / (1.0f + expf(-(a10 + bias)));
    out[base + 257] = 1.0f / (1.0f + expf(-(a11 + bias)));
}

// ---------------- driver ----------------
extern "C" void kernel_launch(void* const* d_in, const int* in_sizes, int n_in,
                              void* d_out, int out_size)
{
    const float* sig   = (const float*)d_in[0];
    const float* trans = (const float*)d_in[1];
    const float* w_d0  = (const float*)d_in[2];
    const float* w_d1  = (const float*)d_in[3];
    const float* g_d1  = (const float*)d_in[4];
    const float* b_d1  = (const float*)d_in[5];
    const float* w_d2  = (const float*)d_in[6];
    const float* g_d2  = (const float*)d_in[7];
    const float* b_d2  = (const float*)d_in[8];
    const float* w_d3  = (const float*)d_in[9];
    const float* g_d3  = (const float*)d_in[10];
    const float* b_d3  = (const float*)d_in[11];
    const float* w_d4  = (const float*)d_in[12];
    const float* w_u4  = (const float*)d_in[13];
    const float* g_u4p = (const float*)d_in[14];
    const float* b_u4p = (const float*)d_in[15];
    const float* w_u3  = (const float*)d_in[16];
    const float* g_u3p = (const float*)d_in[17];
    const float* b_u3p = (const float*)d_in[18];
    const float* w_u2  = (const float*)d_in[19];
    const float* g_u2p = (const float*)d_in[20];
    const float* b_u2p = (const float*)d_in[21];
    const float* w_u1  = (const float*)d_in[22];
    const float* g_u1p = (const float*)d_in[23];
    const float* b_u1p = (const float*)d_in[24];
    const float* w_u0  = (const float*)d_in[25];
    const float* b_u0  = (const float*)d_in[26];

    float* outp = (float*)d_out;
    float* out_rec = outp + IMG;
    int copy_rec = (out_size >= 2 * IMG) ? 1 : 0;

    k_backproject<<<PIX / 256, 256>>>(sig, trans);
    k_minmax_init<<<1, 1>>>();
    k_minmax_reduce<<<256, 256>>>();
    k_normalize<<<(IMG + 255) / 256, 256>>>(out_rec, copy_rec);

    k_conv_d0<<<1024, 256>>>(w_d0);
    k_conv_d1<<<dim3(1024, 2), 256>>>(w_d1);
    k_bns_h1<<<128, 256>>>(g_d1, b_d1);
    k_bna_h1<<<BB*128*4096/256, 256>>>();
    k_conv_d2<<<dim3(256, 4), 256>>>(w_d2);
    k_bns_h2<<<256, 256>>>(g_d2, b_d2);
    k_bna_h2<<<BB*256*1024/256, 256>>>();
    k_conv_d3<<<dim3(64, 8), 256>>>(w_d3);
    k_bns_h3<<<512, 256>>>(g_d3, b_d3);
    k_bna_h3<<<BB*512*256/256, 256>>>();
    k_conv_d4<<<dim3(16, 8), 256>>>(w_d4);

    k_repack<<<(512*512*16 + 255)/256, 256>>>(w_u4, 512, 512);
    k_deconv_u4<<<dim3(16, 8, 4), 256>>>();
    k_bns_u4<<<512, 256>>>(g_u4p, b_u4p);
    k_bna_u4<<<BB*512*256/256, 256>>>();

    k_repack<<<(1024*256*16 + 255)/256, 256>>>(w_u3, 1024, 256);
    k_deconv_u3<<<dim3(64, 4, 4), 256>>>();
    k_bns_u3<<<256, 256>>>(g_u3p, b_u3p);
    k_bna_u3<<<BB*256*1024/256, 256>>>();

    k_repack<<<(512*128*16 + 255)/256, 256>>>(w_u2, 512, 128);
    k_deconv_u2<<<dim3(256, 2, 4), 256>>>();
    k_bns_u2<<<128, 256>>>(g_u2p, b_u2p);
    k_bna_u2<<<BB*128*4096/256, 256>>>();

    k_repack<<<(256*64*16 + 255)/256, 256>>>(w_u1, 256, 64);
    k_deconv_u1<<<dim3(1024, 1, 4), 256>>>();
    k_bns_u1<<<64, 256>>>(g_u1p, b_u1p);
    k_bna_u1<<<BB*64*16384/256, 256>>>();

    k_deconv_u0<<<(BB*128*128 + 255) / 256, 256>>>(w_u0, b_u0, outp);
}

// round 12
// speedup vs baseline: 1.1182x; 1.0811x over previous
#include <cuda_runtime.h>
#include <math.h>

#define BB   16
#define SS   32
#define NTT  2029
#define NN   256
#define PIX  (NN*NN)
#define IMG  (BB*PIX)

__device__ float g_rec [BB*PIX];
__device__ float g_h0  [BB*64 *128*128];
__device__ float g_h1  [BB*128*64 *64 ];
__device__ float g_h2  [BB*256*32 *32 ];
__device__ float g_h3  [BB*512*16 *16 ];
__device__ float g_h4  [BB*512*8  *8  ];
__device__ float g_u4  [BB*512*16 *16 ];
__device__ float g_u3  [BB*256*32 *32 ];
__device__ float g_u2  [BB*128*64 *64 ];
__device__ float g_u1  [BB*64 *128*128];
__device__ float g_wpack[4*512*512*4];
__device__ float g_mm[2];
// per-layer BN affine params: slots h1=0,h2=1,h3=2,u4=3,u3=4,u2=5,u1=6
__device__ float g_scl[7*512];
__device__ float g_shf[7*512];

// ---------------- backprojection (bit-exact passing form — DO NOT TOUCH) -----
__global__ void k_backproject(const float* __restrict__ sig,
                              const float* __restrict__ trans)
{
    int idx = blockIdx.x * blockDim.x + threadIdx.x;
    if (idx >= PIX) return;
    int j = idx & 255, i = idx >> 8;
    const float startf = -0.0125f, stopf = 0.0125f;
    float stepj = __fdiv_rn((float)j, 255.0f);
    float stepi = __fdiv_rn((float)i, 255.0f);
    float cj = __fadd_rn(__fmul_rn(startf, __fsub_rn(1.0f, stepj)), __fmul_rn(stopf, stepj));
    float ci = __fadd_rn(__fmul_rn(startf, __fsub_rn(1.0f, stepi)), __fmul_rn(stopf, stepi));
    float acc[BB];
#pragma unroll
    for (int b = 0; b < BB; b++) acc[b] = 0.f;
    for (int s = 0; s < SS; s++) {
        float dx = __fsub_rn(cj, __ldg(&trans[2*s+0]));
        float dy = __fsub_rn(ci, __ldg(&trans[2*s+1]));
        float dd = __fadd_rn(__fmul_rn(dx, dx), __fmul_rn(dy, dy));
        float d  = __fsqrt_rn(dd);
        float v  = __fadd_rn(__fsub_rn(__fdiv_rn(__fmul_rn(d, 40000000.0f), 1572.0f), 113.0f), 1.0f);
        int t = (int)rintf(v);
        t = max(0, min(t, NTT-1));
        const float* sp = sig + (size_t)t * SS + s;
#pragma unroll
        for (int b = 0; b < BB; b++) acc[b] += __ldg(sp + (size_t)b * NTT * SS);
    }
#pragma unroll
    for (int b = 0; b < BB; b++) g_rec[(size_t)b * PIX + idx] = acc[b] * (1.0f / 32.0f);
}

__device__ void atomicMinF(float* a, float v) {
    int old = __float_as_int(*a);
    while (v < __int_as_float(old)) {
        int prev = atomicCAS((int*)a, old, __float_as_int(v));
        if (prev == old) break; old = prev;
    }
}
__device__ void atomicMaxF(float* a, float v) {
    int old = __float_as_int(*a);
    while (v > __int_as_float(old)) {
        int prev = atomicCAS((int*)a, old, __float_as_int(v));
        if (prev == old) break; old = prev;
    }
}
__global__ void k_minmax_init() { g_mm[0] = INFINITY; g_mm[1] = -INFINITY; }

__global__ void k_minmax_reduce()
{
    float mn = INFINITY, mx = -INFINITY;
    for (int i = blockIdx.x * blockDim.x + threadIdx.x; i < IMG; i += gridDim.x * blockDim.x) {
        float v = g_rec[i]; mn = fminf(mn, v); mx = fmaxf(mx, v);
    }
    __shared__ float smn[256], smx[256];
    int t = threadIdx.x;
    smn[t] = mn; smx[t] = mx;
    __syncthreads();
    for (int o = 128; o > 0; o >>= 1) {
        if (t < o) { smn[t] = fminf(smn[t], smn[t+o]); smx[t] = fmaxf(smx[t], smx[t+o]); }
        __syncthreads();
    }
    if (t == 0) { atomicMinF(&g_mm[0], smn[0]); atomicMaxF(&g_mm[1], smx[0]); }
}

__global__ void k_normalize(float* __restrict__ out_rec, int copy_out)
{
    int i = blockIdx.x * blockDim.x + threadIdx.x;
    if (i >= IMG) return;
    float mn = g_mm[0], mx = g_mm[1];
    float v = __fdiv_rn(__fsub_rn(g_rec[i], mn), __fsub_rn(mx, mn));
    g_rec[i] = v;
    if (copy_out) out_rec[i] = v;
}

// ---------------- conv d0 (Cin=1): direct, taps ascending ----------------
__global__ void __launch_bounds__(256) k_conv_d0(const float* __restrict__ w)
{
    __shared__ float ws[1024];
    for (int i = threadIdx.x; i < 1024; i += 256) ws[i] = w[i];
    __syncthreads();
    int idx = blockIdx.x * 256 + threadIdx.x;        // 16*128*128
    int x = idx & 127, y = (idx >> 7) & 127, b = idx >> 14;
    float patch[16];
#pragma unroll
    for (int t = 0; t < 16; t++) {
        int iy = 2*y - 1 + (t >> 2), ix = 2*x - 1 + (t & 3);
        patch[t] = (iy >= 0 && iy < 256 && ix >= 0 && ix < 256)
                   ? g_rec[b * PIX + iy * 256 + ix] : 0.f;
    }
    float* op = g_h0 + ((size_t)b * 64 << 14) + (y << 7) + x;
    for (int co = 0; co < 64; co++) {
        float a = 0.f;
#pragma unroll
        for (int t = 0; t < 16; t++) a += patch[t] * ws[co * 16 + t];
        op[(size_t)co << 14] = a;
    }
}

// =====================================================================
// conv stride-2 k4 p1 — v1.5 FFMA (proven) + fused input BN (slot BNS)
// B-load: v = raw; if BNS>=0 v = fma(v,sc,sh); if ACT v = lrelu(v)
// =====================================================================
template<int Cin, int Hi, int Wi, int Cout, int ACT, int BNS>
__device__ __forceinline__ void conv_v15(const float* __restrict__ in,
                                         const float* __restrict__ w,
                                         float* __restrict__ out)
{
    constexpr int Ho = Hi >> 1, Wo = Wi >> 1;
    constexpr int HoWo = Ho * Wo;
    constexpr int HiWi = Hi * Wi;
    const int m0 = blockIdx.y * 64;
    const int p0 = blockIdx.x * 64;

    __shared__ __align__(16) float As[2][16][68];
    __shared__ __align__(16) float Bs[2][16][68];

    const int tid  = threadIdx.x;
    const int kk   = tid & 15;
    const int rowq = tid >> 4;
    const int ky = kk >> 2, kx = kk & 3;
    const int tx = kk, ty = rowq;

    int woff[4], bofs[4];
#pragma unroll
    for (int q = 0; q < 4; q++) {
        int n = rowq + 16 * q;
        woff[q] = (m0 + n) * Cin * 16 + kk;
        int p = p0 + n;
        int b = p / HoWo; int r = p - b * HoWo;
        int y = r / Wo;   int x = r - y * Wo;
        int iy = 2*y - 1 + ky, ix = 2*x - 1 + kx;
        bool v = iy >= 0 && iy < Hi && ix >= 0 && ix < Wi;
        bofs[q] = v ? (b * Cin * HiWi + iy * Wi + ix) : -1;
    }

    auto ldb = [&](int cci, int q) -> float {
        float v = 0.f;
        if (bofs[q] >= 0) {
            v = __ldg(in + bofs[q] + (size_t)cci * HiWi);
            if (BNS >= 0)
                v = __fmaf_rn(v, __ldg(g_scl + BNS*512 + cci),
                                 __ldg(g_shf + BNS*512 + cci));
            if (ACT) v = (v >= 0.f) ? v : 0.2f * v;
        }
        return v;
    };

    float aR[4], bR[4];
#pragma unroll
    for (int q = 0; q < 4; q++) { aR[q] = __ldg(w + woff[q]); bR[q] = ldb(0, q); }
#pragma unroll
    for (int q = 0; q < 4; q++) {
        As[0][kk][rowq + 16*q] = aR[q];
        Bs[0][kk][rowq + 16*q] = bR[q];
    }
    __syncthreads();

    float acc[4][4];
#pragma unroll
    for (int i = 0; i < 4; i++)
#pragma unroll
        for (int j = 0; j < 4; j++) acc[i][j] = 0.f;

    int buf = 0;
    for (int cci = 0; cci < Cin; cci++) {
        const bool more = (cci + 1 < Cin);
        if (more) {
            const float* wp = w + (size_t)(cci + 1) * 16;
#pragma unroll
            for (int q = 0; q < 4; q++) { aR[q] = __ldg(wp + woff[q]); bR[q] = ldb(cci + 1, q); }
        }
#pragma unroll
        for (int k = 0; k < 16; k++) {
            float4 a4 = *(const float4*)(&As[buf][k][ty * 4]);
            float4 b4 = *(const float4*)(&Bs[buf][k][tx * 4]);
            float av[4] = {a4.x, a4.y, a4.z, a4.w};
            float bv[4] = {b4.x, b4.y, b4.z, b4.w};
#pragma unroll
            for (int i = 0; i < 4; i++)
#pragma unroll
                for (int j = 0; j < 4; j++)
                    acc[i][j] += av[i] * bv[j];
        }
        if (more) {
            int nb = buf ^ 1;
#pragma unroll
            for (int q = 0; q < 4; q++) {
                As[nb][kk][rowq + 16*q] = aR[q];
                Bs[nb][kk][rowq + 16*q] = bR[q];
            }
            __syncthreads();
            buf = nb;
        }
    }

#pragma unroll
    for (int i = 0; i < 4; i++) {
        int m = m0 + ty * 4 + i;
        int p = p0 + tx * 4;
        int b = p / HoWo; int r = p - b * HoWo;
        float4 v = make_float4(acc[i][0], acc[i][1], acc[i][2], acc[i][3]);
        *(float4*)(&out[(size_t)(b * Cout + m) * HoWo + r]) = v;
    }
}

__global__ void __launch_bounds__(256,3) k_conv_d1(const float* __restrict__ w)
{ conv_v15<64,128,128,128,1,-1>(g_h0, w, g_h1); }
__global__ void __launch_bounds__(256,3) k_conv_d2(const float* __restrict__ w)
{ conv_v15<128,64,64,256,1,0>(g_h1, w, g_h2); }
__global__ void __launch_bounds__(256,3) k_conv_d3(const float* __restrict__ w)
{ conv_v15<256,32,32,512,1,1>(g_h2, w, g_h3); }
__global__ void __launch_bounds__(256,3) k_conv_d4(const float* __restrict__ w)
{ conv_v15<512,16,16,512,1,2>(g_h3, w, g_h4); }

// ---------------- deconv weight repack (per-parity) ----------------
__global__ void k_repack(const float* __restrict__ w, int Cin, int Cout)
{
    int idx = blockIdx.x * blockDim.x + threadIdx.x;
    int total = 4 * Cout * Cin * 4;
    if (idx >= total) return;
    int t = idx & 3, tmp = idx >> 2;
    int ci = tmp % Cin; tmp /= Cin;
    int m = tmp % Cout;
    int pz = tmp / Cout;
    int py = pz >> 1, px = pz & 1;
    int di = t >> 1, dj = t & 1;
    int ky = py ? (1 + 2*di) : (2*di);
    int kx = px ? (1 + 2*dj) : (2*dj);
    g_wpack[idx] = w[(((size_t)ci * Cout + m) * 4 + (3 - ky)) * 4 + (3 - kx)];
}

// =====================================================================
// transposed conv — v1.5 FFMA (proven) + fused input BN for in1/in2
// load: v = relu( bn?(raw) )
// =====================================================================
template<int Cin, int C1, int Hi, int Wi, int Cout, int BNS1, int BNS2>
__device__ __forceinline__ void deconv_v15(const float* __restrict__ in1,
                                           const float* __restrict__ in2,
                                           float* __restrict__ out)
{
    constexpr int HiWi = Hi * Wi;
    constexpr int Wo = 2 * Wi;
    constexpr int HoWo = 4 * HiWi;
    constexpr int C2 = Cin - C1;
    constexpr int NCH = Cin / 4;
    const int pz = blockIdx.z;
    const int py = pz >> 1, px = pz & 1;
    const int m0 = blockIdx.y * 64;
    const int n0 = blockIdx.x * 64;

    __shared__ __align__(16) float As[2][16][68];
    __shared__ __align__(16) float Bs[2][16][68];

    const int tid  = threadIdx.x;
    const int kk   = tid & 15;      // cil*4 + t
    const int rowq = tid >> 4;
    const int cil = kk >> 2, t = kk & 3;
    const int di = t >> 1, dj = t & 1;
    const int tx = kk, ty = rowq;

    int woff[4], pixq[4], bq[4];
#pragma unroll
    for (int q = 0; q < 4; q++) {
        int n = n0 + rowq + 16 * q;
        int b = n / HiWi; int r = n - b * HiWi;
        int yy = r / Wi;  int xx = r - yy * Wi;
        int i = py ? (yy + di) : (yy - 1 + di);
        int j = px ? (xx + dj) : (xx - 1 + dj);
        bool v = i >= 0 && i < Hi && j >= 0 && j < Wi;
        pixq[q] = v ? (i * Wi + j) : -1;
        bq[q] = b;
        int m = m0 + rowq + 16 * q;
        woff[q] = ((pz * Cout + m) * Cin + cil) * 4 + t;
    }

    auto ldb = [&](int ci, int q) -> float {
        float v = 0.f;
        if (pixq[q] >= 0) {
            if (ci < C1) {
                v = __ldg(in1 + (size_t)(bq[q] * C1 + ci) * HiWi + pixq[q]);
                if (BNS1 >= 0)
                    v = __fmaf_rn(v, __ldg(g_scl + BNS1*512 + ci),
                                     __ldg(g_shf + BNS1*512 + ci));
            } else {
                int c2 = ci - C1;
                v = __ldg(in2 + (size_t)(bq[q] * C2 + c2) * HiWi + pixq[q]);
                if (BNS2 >= 0)
                    v = __fmaf_rn(v, __ldg(g_scl + BNS2*512 + c2),
                                     __ldg(g_shf + BNS2*512 + c2));
            }
            v = fmaxf(v, 0.f);
        }
        return v;
    };

    float aR[4], bR[4];
#pragma unroll
    for (int q = 0; q < 4; q++) { aR[q] = g_wpack[woff[q]]; bR[q] = ldb(cil, q); }
#pragma unroll
    for (int q = 0; q < 4; q++) {
        As[0][kk][rowq + 16*q] = aR[q];
        Bs[0][kk][rowq + 16*q] = bR[q];
    }
    __syncthreads();

    float acc[4][4];
#pragma unroll
    for (int i = 0; i < 4; i++)
#pragma unroll
        for (int j = 0; j < 4; j++) acc[i][j] = 0.f;

    int buf = 0;
    for (int s = 0; s < NCH; s++) {
        const bool more = (s + 1 < NCH);
        if (more) {
            int ci = 4 * (s + 1) + cil;
#pragma unroll
            for (int q = 0; q < 4; q++) {
                aR[q] = g_wpack[woff[q] + (s + 1) * 16];
                bR[q] = ldb(ci, q);
            }
        }
#pragma unroll
        for (int k = 0; k < 16; k++) {
            float4 a4 = *(const float4*)(&As[buf][k][ty * 4]);
            float4 b4 = *(const float4*)(&Bs[buf][k][tx * 4]);
            float av[4] = {a4.x, a4.y, a4.z, a4.w};
            float bv[4] = {b4.x, b4.y, b4.z, b4.w};
#pragma unroll
            for (int i = 0; i < 4; i++)
#pragma unroll
                for (int j = 0; j < 4; j++)
                    acc[i][j] += av[i] * bv[j];
        }
        if (more) {
            int nb = buf ^ 1;
#pragma unroll
            for (int q = 0; q < 4; q++) {
                As[nb][kk][rowq + 16*q] = aR[q];
                Bs[nb][kk][rowq + 16*q] = bR[q];
            }
            __syncthreads();
            buf = nb;
        }
    }

#pragma unroll
    for (int i = 0; i < 4; i++) {
        int m = m0 + ty * 4 + i;
#pragma unroll
        for (int j = 0; j < 4; j++) {
            int n = n0 + tx * 4 + j;
            int b = n / HiWi; int r = n - b * HiWi;
            int yy = r / Wi;  int xx = r - yy * Wi;
            int y = 2 * yy + py, x = 2 * xx + px;
            out[(size_t)(b * Cout + m) * HoWo + y * Wo + x] = acc[i][j];
        }
    }
}

__global__ void __launch_bounds__(256,3) k_deconv_u4()
{ deconv_v15<512,512,8,8,512,-1,-1>(g_h4, g_h4, g_u4); }
__global__ void __launch_bounds__(256,3) k_deconv_u3()
{ deconv_v15<1024,512,16,16,256,2,3>(g_h3, g_u4, g_u3); }
__global__ void __launch_bounds__(256,3) k_deconv_u2()
{ deconv_v15<512,256,32,32,128,1,4>(g_h2, g_u3, g_u2); }
__global__ void __launch_bounds__(256,3) k_deconv_u1()
{ deconv_v15<256,128,64,64,64,0,5>(g_h1, g_u2, g_u1); }

// ---------------- batchnorm stats (writes per-layer slot) ----------------
template<int C, int HW, int SLOT>
__device__ __forceinline__ void bn_stats_body(const float* __restrict__ x,
                                              const float* __restrict__ g,
                                              const float* __restrict__ bet)
{
    int c = blockIdx.x;
    constexpr int per = BB * HW;
    double s = 0.0, s2 = 0.0;
    for (int i = threadIdx.x; i < per; i += blockDim.x) {
        int bb = i / HW; int r = i - bb * HW;
        float v = x[(size_t)(bb * C + c) * HW + r];
        s += v; s2 += (double)v * (double)v;
    }
    __shared__ double sh1[256], sh2[256];
    int tl = threadIdx.x;
    sh1[tl] = s; sh2[tl] = s2;
    __syncthreads();
    for (int o = 128; o > 0; o >>= 1) {
        if (tl < o) { sh1[tl] += sh1[tl+o]; sh2[tl] += sh2[tl+o]; }
        __syncthreads();
    }
    if (tl == 0) {
        double m = sh1[0] / per;
        double var = sh2[0] / per - m * m;
        float sc = g[c] * (float)(1.0 / sqrt(var + 1e-5));
        g_scl[SLOT*512 + c] = sc;
        g_shf[SLOT*512 + c] = bet[c] - (float)m * sc;
    }
}

__global__ void k_bns_h1(const float* g, const float* b){ bn_stats_body<128,4096,0>(g_h1,g,b); }
__global__ void k_bns_h2(const float* g, const float* b){ bn_stats_body<256,1024,1>(g_h2,g,b); }
__global__ void k_bns_h3(const float* g, const float* b){ bn_stats_body<512,256,2>(g_h3,g,b); }
__global__ void k_bns_u4(const float* g, const float* b){ bn_stats_body<512,256,3>(g_u4,g,b); }
__global__ void k_bns_u3(const float* g, const float* b){ bn_stats_body<256,1024,4>(g_u3,g,b); }
__global__ void k_bns_u2(const float* g, const float* b){ bn_stats_body<128,4096,5>(g_u2,g,b); }
__global__ void k_bns_u1(const float* g, const float* b){ bn_stats_body<64,16384,6>(g_u1,g,b); }

// ---------------- final deconv u0: 2x2 quad per thread, fused u1-BN ---------
__global__ void k_deconv_u0(const float* __restrict__ w,
                            const float* __restrict__ b0,
                            float* __restrict__ out)
{
    __shared__ float ws[2048];
    for (int i = threadIdx.x; i < 2048; i += blockDim.x) ws[i] = w[i];
    __syncthreads();

    int idx = blockIdx.x * blockDim.x + threadIdx.x;
    if (idx >= BB * 128 * 128) return;
    int xx = idx & 127, yy = (idx >> 7) & 127, b = idx >> 14;

    const float* h0p = g_h0 + (size_t)b * 64 * 16384;
    const float* u1p = g_u1 + (size_t)b * 64 * 16384;
    float a00 = 0.f, a01 = 0.f, a10 = 0.f, a11 = 0.f;

    for (int ci = 0; ci < 128; ci++) {
        const bool isU = (ci >= 64);
        const float* src = isU ? (u1p + (ci - 64) * 16384) : (h0p + ci * 16384);
        float sc = 1.f, sh = 0.f;
        if (isU) { sc = __ldg(g_scl + 6*512 + (ci - 64)); sh = __ldg(g_shf + 6*512 + (ci - 64)); }
        float v[3][3];
#pragma unroll
        for (int dy = 0; dy < 3; dy++) {
            int i = yy - 1 + dy;
#pragma unroll
            for (int dxx = 0; dxx < 3; dxx++) {
                int jx = xx - 1 + dxx;
                float r = 0.f;
                if (i >= 0 && i < 128 && jx >= 0 && jx < 128) {
                    r = __ldg(src + i * 128 + jx);
                    if (isU) r = __fmaf_rn(r, sc, sh);
                    r = fmaxf(r, 0.f);
                }
                v[dy][dxx] = r;
            }
        }
        const float* wsr = ws + ci * 16;
#pragma unroll
        for (int di = 0; di < 2; di++)
#pragma unroll
            for (int dj = 0; dj < 2; dj++)
                a00 += v[di][dj] * wsr[(3 - 2*di) * 4 + (3 - 2*dj)];
#pragma unroll
        for (int di = 0; di < 2; di++)
#pragma unroll
            for (int dj = 0; dj < 2; dj++)
                a01 += v[di][dj+1] * wsr[(3 - 2*di) * 4 + (2 - 2*dj)];
#pragma unroll
        for (int di = 0; di < 2; di++)
#pragma unroll
            for (int dj = 0; dj < 2; dj++)
                a10 += v[di+1][dj] * wsr[(2 - 2*di) * 4 + (3 - 2*dj)];
#pragma unroll
        for (int di = 0; di < 2; di++)
#pragma unroll
            for (int dj = 0; dj < 2; dj++)
                a11 += v[di+1][dj+1] * wsr[(2 - 2*di) * 4 + (2 - 2*dj)];
    }

    float bias = __ldg(&b0[0]);
    int base = b * PIX + (2 * yy) * 256 + 2 * xx;
    out[base]       = 1.0f / (1.0f + expf(-(a00 + bias)));
    out[base + 1]   = 1.0f / (1.0f + expf(-(a01 + bias)));
    out[base + 256] = 1.0f / (1.0f + expf(-(a10 + bias)));
    out[base + 257] = 1.0f / (1.0f + expf(-(a11 + bias)));
}

// ---------------- driver ----------------
extern "C" void kernel_launch(void* const* d_in, const int* in_sizes, int n_in,
                              void* d_out, int out_size)
{
    const float* sig   = (const float*)d_in[0];
    const float* trans = (const float*)d_in[1];
    const float* w_d0  = (const float*)d_in[2];
    const float* w_d1  = (const float*)d_in[3];
    const float* g_d1  = (const float*)d_in[4];
    const float* b_d1  = (const float*)d_in[5];
    const float* w_d2  = (const float*)d_in[6];
    const float* g_d2  = (const float*)d_in[7];
    const float* b_d2  = (const float*)d_in[8];
    const float* w_d3  = (const float*)d_in[9];
    const float* g_d3  = (const float*)d_in[10];
    const float* b_d3  = (const float*)d_in[11];
    const float* w_d4  = (const float*)d_in[12];
    const float* w_u4  = (const float*)d_in[13];
    const float* g_u4p = (const float*)d_in[14];
    const float* b_u4p = (const float*)d_in[15];
    const float* w_u3  = (const float*)d_in[16];
    const float* g_u3p = (const float*)d_in[17];
    const float* b_u3p = (const float*)d_in[18];
    const float* w_u2  = (const float*)d_in[19];
    const float* g_u2p = (const float*)d_in[20];
    const float* b_u2p = (const float*)d_in[21];
    const float* w_u1  = (const float*)d_in[22];
    const float* g_u1p = (const float*)d_in[23];
    const float* b_u1p = (const float*)d_in[24];
    const float* w_u0  = (const float*)d_in[25];
    const float* b_u0  = (const float*)d_in[26];

    float* outp = (float*)d_out;
    float* out_rec = outp + IMG;
    int copy_rec = (out_size >= 2 * IMG) ? 1 : 0;

    k_backproject<<<PIX / 256, 256>>>(sig, trans);
    k_minmax_init<<<1, 1>>>();
    k_minmax_reduce<<<256, 256>>>();
    k_normalize<<<(IMG + 255) / 256, 256>>>(out_rec, copy_rec);

    k_conv_d0<<<1024, 256>>>(w_d0);
    k_conv_d1<<<dim3(1024, 2), 256>>>(w_d1);
    k_bns_h1<<<128, 256>>>(g_d1, b_d1);
    k_conv_d2<<<dim3(256, 4), 256>>>(w_d2);
    k_bns_h2<<<256, 256>>>(g_d2, b_d2);
    k_conv_d3<<<dim3(64, 8), 256>>>(w_d3);
    k_bns_h3<<<512, 256>>>(g_d3, b_d3);
    k_conv_d4<<<dim3(16, 8), 256>>>(w_d4);

    k_repack<<<(512*512*16 + 255)/256, 256>>>(w_u4, 512, 512);
    k_deconv_u4<<<dim3(16, 8, 4), 256>>>();
    k_bns_u4<<<512, 256>>>(g_u4p, b_u4p);

    k_repack<<<(1024*256*16 + 255)/256, 256>>>(w_u3, 1024, 256);
    k_deconv_u3<<<dim3(64, 4, 4), 256>>>();
    k_bns_u3<<<256, 256>>>(g_u3p, b_u3p);

    k_repack<<<(512*128*16 + 255)/256, 256>>>(w_u2, 512, 128);
    k_deconv_u2<<<dim3(256, 2, 4), 256>>>();
    k_bns_u2<<<128, 256>>>(g_u2p, b_u2p);

    k_repack<<<(256*64*16 + 255)/256, 256>>>(w_u1, 256, 64);
    k_deconv_u1<<<dim3(1024, 1, 4), 256>>>();
    k_bns_u1<<<64, 256>>>(g_u1p, b_u1p);

    k_deconv_u0<<<(BB*128*128 + 255) / 256, 256>>>(w_u0, b_u0, outp);
}

// round 13
// speedup vs baseline: 1.1662x; 1.0429x over previous
#include <cuda_runtime.h>
#include <math.h>

#define BB   16
#define SS   32
#define NTT  2029
#define NN   256
#define PIX  (NN*NN)
#define IMG  (BB*PIX)

__device__ float g_rec [BB*PIX];
__device__ float g_h0  [BB*64 *128*128];
__device__ float g_h1  [BB*128*64 *64 ];
__device__ float g_h2  [BB*256*32 *32 ];
__device__ float g_h3  [BB*512*16 *16 ];
__device__ float g_h4  [BB*512*8  *8  ];
__device__ float g_u4  [BB*512*16 *16 ];
__device__ float g_u3  [BB*256*32 *32 ];
__device__ float g_u2  [BB*128*64 *64 ];
__device__ float g_u1  [BB*64 *128*128];
__device__ float g_wpack[4*512*512*4];
__device__ float g_mm[2];
// BN slots: h1=0,h2=1,h3=2,u4=3,u3=4,u2=5,u1=6
__device__ float g_scl[7*512];
__device__ float g_shf[7*512];

// ---------------- backprojection (bit-exact passing form — DO NOT TOUCH) -----
__global__ void k_backproject(const float* __restrict__ sig,
                              const float* __restrict__ trans)
{
    int idx = blockIdx.x * blockDim.x + threadIdx.x;
    if (idx >= PIX) return;
    int j = idx & 255, i = idx >> 8;
    const float startf = -0.0125f, stopf = 0.0125f;
    float stepj = __fdiv_rn((float)j, 255.0f);
    float stepi = __fdiv_rn((float)i, 255.0f);
    float cj = __fadd_rn(__fmul_rn(startf, __fsub_rn(1.0f, stepj)), __fmul_rn(stopf, stepj));
    float ci = __fadd_rn(__fmul_rn(startf, __fsub_rn(1.0f, stepi)), __fmul_rn(stopf, stepi));
    float acc[BB];
#pragma unroll
    for (int b = 0; b < BB; b++) acc[b] = 0.f;
    for (int s = 0; s < SS; s++) {
        float dx = __fsub_rn(cj, __ldg(&trans[2*s+0]));
        float dy = __fsub_rn(ci, __ldg(&trans[2*s+1]));
        float dd = __fadd_rn(__fmul_rn(dx, dx), __fmul_rn(dy, dy));
        float d  = __fsqrt_rn(dd);
        float v  = __fadd_rn(__fsub_rn(__fdiv_rn(__fmul_rn(d, 40000000.0f), 1572.0f), 113.0f), 1.0f);
        int t = (int)rintf(v);
        t = max(0, min(t, NTT-1));
        const float* sp = sig + (size_t)t * SS + s;
#pragma unroll
        for (int b = 0; b < BB; b++) acc[b] += __ldg(sp + (size_t)b * NTT * SS);
    }
#pragma unroll
    for (int b = 0; b < BB; b++) g_rec[(size_t)b * PIX + idx] = acc[b] * (1.0f / 32.0f);
}

__device__ void atomicMinF(float* a, float v) {
    int old = __float_as_int(*a);
    while (v < __int_as_float(old)) {
        int prev = atomicCAS((int*)a, old, __float_as_int(v));
        if (prev == old) break; old = prev;
    }
}
__device__ void atomicMaxF(float* a, float v) {
    int old = __float_as_int(*a);
    while (v > __int_as_float(old)) {
        int prev = atomicCAS((int*)a, old, __float_as_int(v));
        if (prev == old) break; old = prev;
    }
}
__global__ void k_minmax_init() { g_mm[0] = INFINITY; g_mm[1] = -INFINITY; }

__global__ void k_minmax_reduce()
{
    float mn = INFINITY, mx = -INFINITY;
    for (int i = blockIdx.x * blockDim.x + threadIdx.x; i < IMG; i += gridDim.x * blockDim.x) {
        float v = g_rec[i]; mn = fminf(mn, v); mx = fmaxf(mx, v);
    }
    __shared__ float smn[256], smx[256];
    int t = threadIdx.x;
    smn[t] = mn; smx[t] = mx;
    __syncthreads();
    for (int o = 128; o > 0; o >>= 1) {
        if (t < o) { smn[t] = fminf(smn[t], smn[t+o]); smx[t] = fmaxf(smx[t], smx[t+o]); }
        __syncthreads();
    }
    if (t == 0) { atomicMinF(&g_mm[0], smn[0]); atomicMaxF(&g_mm[1], smx[0]); }
}

__global__ void k_normalize(float* __restrict__ out_rec, int copy_out)
{
    int i = blockIdx.x * blockDim.x + threadIdx.x;
    if (i >= IMG) return;
    float mn = g_mm[0], mx = g_mm[1];
    float v = __fdiv_rn(__fsub_rn(g_rec[i], mn), __fsub_rn(mx, mn));
    g_rec[i] = v;
    if (copy_out) out_rec[i] = v;
}

// ---------------- conv d0 (Cin=1): direct, taps ascending (R12-proven) -------
__global__ void __launch_bounds__(256) k_conv_d0(const float* __restrict__ w)
{
    __shared__ float ws[1024];
    for (int i = threadIdx.x; i < 1024; i += 256) ws[i] = w[i];
    __syncthreads();
    int idx = blockIdx.x * 256 + threadIdx.x;        // 16*128*128
    int x = idx & 127, y = (idx >> 7) & 127, b = idx >> 14;
    float patch[16];
#pragma unroll
    for (int t = 0; t < 16; t++) {
        int iy = 2*y - 1 + (t >> 2), ix = 2*x - 1 + (t & 3);
        patch[t] = (iy >= 0 && iy < 256 && ix >= 0 && ix < 256)
                   ? g_rec[b * PIX + iy * 256 + ix] : 0.f;
    }
    float* op = g_h0 + ((size_t)b * 64 << 14) + (y << 7) + x;
    for (int co = 0; co < 64; co++) {
        float a = 0.f;
#pragma unroll
        for (int t = 0; t < 16; t++) a += patch[t] * ws[co * 16 + t];
        op[(size_t)co << 14] = a;
    }
}

// =====================================================================
// conv stride-2 k4 p1 — v1.5 FFMA + hoisted fused BN + NT template
// =====================================================================
template<int Cin, int Hi, int Wi, int Cout, int ACT, int BNS, int NT>
__device__ __forceinline__ void conv_v15(const float* __restrict__ in,
                                         const float* __restrict__ w,
                                         float* __restrict__ out)
{
    constexpr int Ho = Hi >> 1, Wo = Wi >> 1;
    constexpr int HoWo = Ho * Wo;
    constexpr int HiWi = Hi * Wi;
    constexpr int NQ = NT / 16;      // B cols per staging thread
    constexpr int NJ = NT / 16;      // acc cols per compute thread
    const int m0 = blockIdx.y * 64;
    const int p0 = blockIdx.x * NT;

    __shared__ __align__(16) float As[2][16][68];
    __shared__ __align__(16) float Bs[2][16][NT + 4];

    const int tid  = threadIdx.x;
    const int kk   = tid & 15;
    const int rowq = tid >> 4;
    const int ky = kk >> 2, kx = kk & 3;
    const int tx = kk, ty = rowq;

    int woff[4];
#pragma unroll
    for (int q = 0; q < 4; q++)
        woff[q] = (m0 + rowq + 16 * q) * Cin * 16 + kk;

    int bofs[NQ];
#pragma unroll
    for (int q = 0; q < NQ; q++) {
        int p = p0 + rowq + 16 * q;
        int b = p / HoWo; int r = p - b * HoWo;
        int y = r / Wo;   int x = r - y * Wo;
        int iy = 2*y - 1 + ky, ix = 2*x - 1 + kx;
        bool v = iy >= 0 && iy < Hi && ix >= 0 && ix < Wi;
        bofs[q] = v ? (b * Cin * HiWi + iy * Wi + ix) : -1;
    }

    float sc = 1.f, sh = 0.f;
    if (BNS >= 0) { sc = __ldg(g_scl + BNS*512); sh = __ldg(g_shf + BNS*512); }

    float aR[4], bR[NQ];
#pragma unroll
    for (int q = 0; q < 4; q++) aR[q] = __ldg(w + woff[q]);
#pragma unroll
    for (int q = 0; q < NQ; q++) {
        float v = 0.f;
        if (bofs[q] >= 0) {
            v = __ldg(in + bofs[q]);
            if (BNS >= 0) v = __fmaf_rn(v, sc, sh);
            if (ACT) v = (v >= 0.f) ? v : 0.2f * v;
        }
        bR[q] = v;
    }
#pragma unroll
    for (int q = 0; q < 4;  q++) As[0][kk][rowq + 16*q] = aR[q];
#pragma unroll
    for (int q = 0; q < NQ; q++) Bs[0][kk][rowq + 16*q] = bR[q];
    __syncthreads();

    float acc[4][NJ];
#pragma unroll
    for (int i = 0; i < 4; i++)
#pragma unroll
        for (int j = 0; j < NJ; j++) acc[i][j] = 0.f;

    int buf = 0;
    for (int cci = 0; cci < Cin; cci++) {
        const bool more = (cci + 1 < Cin);
        if (more) {
            if (BNS >= 0) {
                sc = __ldg(g_scl + BNS*512 + cci + 1);
                sh = __ldg(g_shf + BNS*512 + cci + 1);
            }
            const float* wp = w + (size_t)(cci + 1) * 16;
            const float* ip = in + (size_t)(cci + 1) * HiWi;
#pragma unroll
            for (int q = 0; q < 4; q++) aR[q] = __ldg(wp + woff[q]);
#pragma unroll
            for (int q = 0; q < NQ; q++) {
                float v = 0.f;
                if (bofs[q] >= 0) {
                    v = __ldg(ip + bofs[q]);
                    if (BNS >= 0) v = __fmaf_rn(v, sc, sh);
                    if (ACT) v = (v >= 0.f) ? v : 0.2f * v;
                }
                bR[q] = v;
            }
        }
#pragma unroll
        for (int k = 0; k < 16; k++) {
            float4 a4 = *(const float4*)(&As[buf][k][ty * 4]);
            float av[4] = {a4.x, a4.y, a4.z, a4.w};
            float bv[NJ];
            if (NJ == 4) {
                float4 b4 = *(const float4*)(&Bs[buf][k][tx * 4]);
                bv[0] = b4.x; bv[1] = b4.y; bv[2] = b4.z; bv[3 % NJ] = b4.w;
            } else {
                float2 b2 = *(const float2*)(&Bs[buf][k][tx * 2]);
                bv[0] = b2.x; bv[1 % NJ] = b2.y;
            }
#pragma unroll
            for (int i = 0; i < 4; i++)
#pragma unroll
                for (int j = 0; j < NJ; j++)
                    acc[i][j] += av[i] * bv[j];
        }
        if (more) {
            int nb = buf ^ 1;
#pragma unroll
            for (int q = 0; q < 4;  q++) As[nb][kk][rowq + 16*q] = aR[q];
#pragma unroll
            for (int q = 0; q < NQ; q++) Bs[nb][kk][rowq + 16*q] = bR[q];
            __syncthreads();
            buf = nb;
        }
    }

#pragma unroll
    for (int i = 0; i < 4; i++) {
        int m = m0 + ty * 4 + i;
        int p = p0 + tx * NJ;
        int b = p / HoWo; int r = p - b * HoWo;
        float* dst = &out[(size_t)(b * Cout + m) * HoWo + r];
        if (NJ == 4) {
            float4 v = make_float4(acc[i][0], acc[i][1], acc[i][2 % NJ], acc[i][3 % NJ]);
            *(float4*)dst = v;
        } else {
            float2 v = make_float2(acc[i][0], acc[i][1 % NJ]);
            *(float2*)dst = v;
        }
    }
}

__global__ void __launch_bounds__(256,3) k_conv_d1(const float* __restrict__ w)
{ conv_v15<64,128,128,128,1,-1,64>(g_h0, w, g_h1); }
__global__ void __launch_bounds__(256,3) k_conv_d2(const float* __restrict__ w)
{ conv_v15<128,64,64,256,1,0,64>(g_h1, w, g_h2); }
__global__ void __launch_bounds__(256,3) k_conv_d3(const float* __restrict__ w)
{ conv_v15<256,32,32,512,1,1,64>(g_h2, w, g_h3); }
__global__ void __launch_bounds__(256,3) k_conv_d4(const float* __restrict__ w)
{ conv_v15<512,16,16,512,1,2,32>(g_h3, w, g_h4); }

// ---------------- deconv weight repack (per-parity) ----------------
__global__ void k_repack(const float* __restrict__ w, int Cin, int Cout)
{
    int idx = blockIdx.x * blockDim.x + threadIdx.x;
    int total = 4 * Cout * Cin * 4;
    if (idx >= total) return;
    int t = idx & 3, tmp = idx >> 2;
    int ci = tmp % Cin; tmp /= Cin;
    int m = tmp % Cout;
    int pz = tmp / Cout;
    int py = pz >> 1, px = pz & 1;
    int di = t >> 1, dj = t & 1;
    int ky = py ? (1 + 2*di) : (2*di);
    int kx = px ? (1 + 2*dj) : (2*dj);
    g_wpack[idx] = w[(((size_t)ci * Cout + m) * 4 + (3 - ky)) * 4 + (3 - kx)];
}

// =====================================================================
// transposed conv — v1.5 FFMA + hoisted fused BN for in1/in2
// =====================================================================
template<int Cin, int C1, int Hi, int Wi, int Cout, int BNS1, int BNS2>
__device__ __forceinline__ void deconv_v15(const float* __restrict__ in1,
                                           const float* __restrict__ in2,
                                           float* __restrict__ out)
{
    constexpr int HiWi = Hi * Wi;
    constexpr int Wo = 2 * Wi;
    constexpr int HoWo = 4 * HiWi;
    constexpr int C2 = Cin - C1;
    constexpr int NCH = Cin / 4;
    const int pz = blockIdx.z;
    const int py = pz >> 1, px = pz & 1;
    const int m0 = blockIdx.y * 64;
    const int n0 = blockIdx.x * 64;

    __shared__ __align__(16) float As[2][16][68];
    __shared__ __align__(16) float Bs[2][16][68];

    const int tid  = threadIdx.x;
    const int kk   = tid & 15;
    const int rowq = tid >> 4;
    const int cil = kk >> 2, t = kk & 3;
    const int di = t >> 1, dj = t & 1;
    const int tx = kk, ty = rowq;

    int woff[4], pixq[4], bq[4];
#pragma unroll
    for (int q = 0; q < 4; q++) {
        int n = n0 + rowq + 16 * q;
        int b = n / HiWi; int r = n - b * HiWi;
        int yy = r / Wi;  int xx = r - yy * Wi;
        int i = py ? (yy + di) : (yy - 1 + di);
        int j = px ? (xx + dj) : (xx - 1 + dj);
        bool v = i >= 0 && i < Hi && j >= 0 && j < Wi;
        pixq[q] = v ? (i * Wi + j) : -1;
        bq[q] = b;
        int m = m0 + rowq + 16 * q;
        woff[q] = ((pz * Cout + m) * Cin + cil) * 4 + t;
    }

    // per-chunk hoisted BN params for this thread's channel
    float sc, sh;
    const float* srcb;   // channel base (without batch offset)
    int cstride;         // C of active tensor
    auto setch = [&](int ci) {
        if (ci < C1) {
            srcb = in1; cstride = C1;
            if (BNS1 >= 0) { sc = __ldg(g_scl + BNS1*512 + ci); sh = __ldg(g_shf + BNS1*512 + ci); }
            else { sc = 1.f; sh = 0.f; }
        } else {
            int c2 = ci - C1;
            srcb = in2 + (size_t)c2 * HiWi; cstride = C2;   // note: base shifted by channel
            if (BNS2 >= 0) { sc = __ldg(g_scl + BNS2*512 + c2); sh = __ldg(g_shf + BNS2*512 + c2); }
            else { sc = 1.f; sh = 0.f; }
        }
    };
    // channel pointer for tensor-1 handled uniformly: for in1 we shift by ci too
    int curci = cil;

    auto ldb = [&](int ci, int q) -> float {
        float v = 0.f;
        if (pixq[q] >= 0) {
            const float* s;
            if (ci < C1) s = in1 + (size_t)(bq[q] * C1 + ci) * HiWi;
            else         s = in2 + (size_t)(bq[q] * C2 + (ci - C1)) * HiWi;
            v = __ldg(s + pixq[q]);
            v = __fmaf_rn(v, sc, sh);
            v = fmaxf(v, 0.f);
        }
        return v;
    };

    setch(curci);
    float aR[4], bR[4];
#pragma unroll
    for (int q = 0; q < 4; q++) { aR[q] = g_wpack[woff[q]]; bR[q] = ldb(curci, q); }
#pragma unroll
    for (int q = 0; q < 4; q++) {
        As[0][kk][rowq + 16*q] = aR[q];
        Bs[0][kk][rowq + 16*q] = bR[q];
    }
    __syncthreads();

    float acc[4][4];
#pragma unroll
    for (int i = 0; i < 4; i++)
#pragma unroll
        for (int j = 0; j < 4; j++) acc[i][j] = 0.f;

    int buf = 0;
    for (int s = 0; s < NCH; s++) {
        const bool more = (s + 1 < NCH);
        if (more) {
            int ci = 4 * (s + 1) + cil;
            setch(ci);
#pragma unroll
            for (int q = 0; q < 4; q++) {
                aR[q] = g_wpack[woff[q] + (s + 1) * 16];
                bR[q] = ldb(ci, q);
            }
        }
#pragma unroll
        for (int k = 0; k < 16; k++) {
            float4 a4 = *(const float4*)(&As[buf][k][ty * 4]);
            float4 b4 = *(const float4*)(&Bs[buf][k][tx * 4]);
            float av[4] = {a4.x, a4.y, a4.z, a4.w};
            float bv[4] = {b4.x, b4.y, b4.z, b4.w};
#pragma unroll
            for (int i = 0; i < 4; i++)
#pragma unroll
                for (int j = 0; j < 4; j++)
                    acc[i][j] += av[i] * bv[j];
        }
        if (more) {
            int nb = buf ^ 1;
#pragma unroll
            for (int q = 0; q < 4; q++) {
                As[nb][kk][rowq + 16*q] = aR[q];
                Bs[nb][kk][rowq + 16*q] = bR[q];
            }
            __syncthreads();
            buf = nb;
        }
    }

#pragma unroll
    for (int i = 0; i < 4; i++) {
        int m = m0 + ty * 4 + i;
#pragma unroll
        for (int j = 0; j < 4; j++) {
            int n = n0 + tx * 4 + j;
            int b = n / HiWi; int r = n - b * HiWi;
            int yy = r / Wi;  int xx = r - yy * Wi;
            int y = 2 * yy + py, x = 2 * xx + px;
            out[(size_t)(b * Cout + m) * HoWo + y * Wo + x] = acc[i][j];
        }
    }
}

__global__ void __launch_bounds__(256,3) k_deconv_u4()
{ deconv_v15<512,512,8,8,512,-1,-1>(g_h4, g_h4, g_u4); }
__global__ void __launch_bounds__(256,3) k_deconv_u3()
{ deconv_v15<1024,512,16,16,256,2,3>(g_h3, g_u4, g_u3); }
__global__ void __launch_bounds__(256,3) k_deconv_u2()
{ deconv_v15<512,256,32,32,128,1,4>(g_h2, g_u3, g_u2); }
__global__ void __launch_bounds__(256,3) k_deconv_u1()
{ deconv_v15<256,128,64,64,64,0,5>(g_h1, g_u2, g_u1); }

// ---------------- batchnorm stats (writes per-layer slot) ----------------
template<int C, int HW, int SLOT>
__device__ __forceinline__ void bn_stats_body(const float* __restrict__ x,
                                              const float* __restrict__ g,
                                              const float* __restrict__ bet)
{
    int c = blockIdx.x;
    constexpr int per = BB * HW;
    double s = 0.0, s2 = 0.0;
    for (int i = threadIdx.x; i < per; i += blockDim.x) {
        int bb = i / HW; int r = i - bb * HW;
        float v = x[(size_t)(bb * C + c) * HW + r];
        s += v; s2 += (double)v * (double)v;
    }
    __shared__ double sh1[256], sh2[256];
    int tl = threadIdx.x;
    sh1[tl] = s; sh2[tl] = s2;
    __syncthreads();
    for (int o = 128; o > 0; o >>= 1) {
        if (tl < o) { sh1[tl] += sh1[tl+o]; sh2[tl] += sh2[tl+o]; }
        __syncthreads();
    }
    if (tl == 0) {
        double m = sh1[0] / per;
        double var = sh2[0] / per - m * m;
        float sc = g[c] * (float)(1.0 / sqrt(var + 1e-5));
        g_scl[SLOT*512 + c] = sc;
        g_shf[SLOT*512 + c] = bet[c] - (float)m * sc;
    }
}

__global__ void k_bns_h1(const float* g, const float* b){ bn_stats_body<128,4096,0>(g_h1,g,b); }
__global__ void k_bns_h2(const float* g, const float* b){ bn_stats_body<256,1024,1>(g_h2,g,b); }
__global__ void k_bns_h3(const float* g, const float* b){ bn_stats_body<512,256,2>(g_h3,g,b); }
__global__ void k_bns_u4(const float* g, const float* b){ bn_stats_body<512,256,3>(g_u4,g,b); }
__global__ void k_bns_u3(const float* g, const float* b){ bn_stats_body<256,1024,4>(g_u3,g,b); }
__global__ void k_bns_u2(const float* g, const float* b){ bn_stats_body<128,4096,5>(g_u2,g,b); }
__global__ void k_bns_u1(const float* g, const float* b){ bn_stats_body<64,16384,6>(g_u1,g,b); }

// ---------------- final deconv u0: 2x2 quad per thread, fused u1-BN ---------
__global__ void k_deconv_u0(const float* __restrict__ w,
                            const float* __restrict__ b0,
                            float* __restrict__ out)
{
    __shared__ float ws[2048];
    for (int i = threadIdx.x; i < 2048; i += blockDim.x) ws[i] = w[i];
    __syncthreads();

    int idx = blockIdx.x * blockDim.x + threadIdx.x;
    if (idx >= BB * 128 * 128) return;
    int xx = idx & 127, yy = (idx >> 7) & 127, b = idx >> 14;

    const float* h0p = g_h0 + (size_t)b * 64 * 16384;
    const float* u1p = g_u1 + (size_t)b * 64 * 16384;
    float a00 = 0.f, a01 = 0.f, a10 = 0.f, a11 = 0.f;

    for (int ci = 0; ci < 128; ci++) {
        const bool isU = (ci >= 64);
        const float* src = isU ? (u1p + (ci - 64) * 16384) : (h0p + ci * 16384);
        float sc = 1.f, sh = 0.f;
        if (isU) { sc = __ldg(g_scl + 6*512 + (ci - 64)); sh = __ldg(g_shf + 6*512 + (ci - 64)); }
        float v[3][3];
#pragma unroll
        for (int dy = 0; dy < 3; dy++) {
            int i = yy - 1 + dy;
#pragma unroll
            for (int dxx = 0; dxx < 3; dxx++) {
                int jx = xx - 1 + dxx;
                float r = 0.f;
                if (i >= 0 && i < 128 && jx >= 0 && jx < 128) {
                    r = __ldg(src + i * 128 + jx);
                    if (isU) r = __fmaf_rn(r, sc, sh);
                    r = fmaxf(r, 0.f);
                }
                v[dy][dxx] = r;
            }
        }
        const float* wsr = ws + ci * 16;
#pragma unroll
        for (int di = 0; di < 2; di++)
#pragma unroll
            for (int dj = 0; dj < 2; dj++)
                a00 += v[di][dj] * wsr[(3 - 2*di) * 4 + (3 - 2*dj)];
#pragma unroll
        for (int di = 0; di < 2; di++)
#pragma unroll
            for (int dj = 0; dj < 2; dj++)
                a01 += v[di][dj+1] * wsr[(3 - 2*di) * 4 + (2 - 2*dj)];
#pragma unroll
        for (int di = 0; di < 2; di++)
#pragma unroll
            for (int dj = 0; dj < 2; dj++)
                a10 += v[di+1][dj] * wsr[(2 - 2*di) * 4 + (3 - 2*dj)];
#pragma unroll
        for (int di = 0; di < 2; di++)
#pragma unroll
            for (int dj = 0; dj < 2; dj++)
                a11 += v[di+1][dj+1] * wsr[(2 - 2*di) * 4 + (2 - 2*dj)];
    }

    float bias = __ldg(&b0[0]);
    int base = b * PIX + (2 * yy) * 256 + 2 * xx;
    out[base]       = 1.0f / (1.0f + expf(-(a00 + bias)));
    out[base + 1]   = 1.0f / (1.0f + expf(-(a01 + bias)));
    out[base + 256] = 1.0f / (1.0f + expf(-(a10 + bias)));
    out[base + 257] = 1.0f / (1.0f + expf(-(a11 + bias)));
}

// ---------------- driver ----------------
extern "C" void kernel_launch(void* const* d_in, const int* in_sizes, int n_in,
                              void* d_out, int out_size)
{
    const float* sig   = (const float*)d_in[0];
    const float* trans = (const float*)d_in[1];
    const float* w_d0  = (const float*)d_in[2];
    const float* w_d1  = (const float*)d_in[3];
    const float* g_d1  = (const float*)d_in[4];
    const float* b_d1  = (const float*)d_in[5];
    const float* w_d2  = (const float*)d_in[6];
    const float* g_d2  = (const float*)d_in[7];
    const float* b_d2  = (const float*)d_in[8];
    const float* w_d3  = (const float*)d_in[9];
    const float* g_d3  = (const float*)d_in[10];
    const float* b_d3  = (const float*)d_in[11];
    const float* w_d4  = (const float*)d_in[12];
    const float* w_u4  = (const float*)d_in[13];
    const float* g_u4p = (const float*)d_in[14];
    const float* b_u4p = (const float*)d_in[15];
    const float* w_u3  = (const float*)d_in[16];
    const float* g_u3p = (const float*)d_in[17];
    const float* b_u3p = (const float*)d_in[18];
    const float* w_u2  = (const float*)d_in[19];
    const float* g_u2p = (const float*)d_in[20];
    const float* b_u2p = (const float*)d_in[21];
    const float* w_u1  = (const float*)d_in[22];
    const float* g_u1p = (const float*)d_in[23];
    const float* b_u1p = (const float*)d_in[24];
    const float* w_u0  = (const float*)d_in[25];
    const float* b_u0  = (const float*)d_in[26];

    float* outp = (float*)d_out;
    float* out_rec = outp + IMG;
    int copy_rec = (out_size >= 2 * IMG) ? 1 : 0;

    k_backproject<<<PIX / 256, 256>>>(sig, trans);
    k_minmax_init<<<1, 1>>>();
    k_minmax_reduce<<<256, 256>>>();
    k_normalize<<<(IMG + 255) / 256, 256>>>(out_rec, copy_rec);

    k_conv_d0<<<1024, 256>>>(w_d0);
    k_conv_d1<<<dim3(1024, 2), 256>>>(w_d1);
    k_bns_h1<<<128, 256>>>(g_d1, b_d1);
    k_conv_d2<<<dim3(256, 4), 256>>>(w_d2);
    k_bns_h2<<<256, 256>>>(g_d2, b_d2);
    k_conv_d3<<<dim3(64, 8), 256>>>(w_d3);
    k_bns_h3<<<512, 256>>>(g_d3, b_d3);
    k_conv_d4<<<dim3(32, 8), 256>>>(w_d4);     // NT=32 variant

    k_repack<<<(512*512*16 + 255)/256, 256>>>(w_u4, 512, 512);
    k_deconv_u4<<<dim3(16, 8, 4), 256>>>();
    k_bns_u4<<<512, 256>>>(g_u4p, b_u4p);

    k_repack<<<(1024*256*16 + 255)/256, 256>>>(w_u3, 1024, 256);
    k_deconv_u3<<<dim3(64, 4, 4), 256>>>();
    k_bns_u3<<<256, 256>>>(g_u3p, b_u3p);

    k_repack<<<(512*128*16 + 255)/256, 256>>>(w_u2, 512, 128);
    k_deconv_u2<<<dim3(256, 2, 4), 256>>>();
    k_bns_u2<<<128, 256>>>(g_u2p, b_u2p);

    k_repack<<<(256*64*16 + 255)/256, 256>>>(w_u1, 256, 64);
    k_deconv_u1<<<dim3(1024, 1, 4), 256>>>();
    k_bns_u1<<<64, 256>>>(g_u1p, b_u1p);

    k_deconv_u0<<<(BB*128*128 + 255) / 256, 256>>>(w_u0, b_u0, outp);
}